// round 1
// baseline (speedup 1.0000x reference)
#include <cuda_runtime.h>

#define DIM    768
#define NH     12
#define HD     64
#define BATCH  16
#define SEQ    784
#define M_TOTAL (BATCH * SEQ)      /* 12544 */
#define QKV_N   (3 * DIM)          /* 2304  */

/* ---------------- scratch (allocation-free rule: __device__ globals) ------- */
__device__ float g_qkv[(size_t)M_TOTAL * QKV_N];   /* [M, 3*DIM] == [b,n,3,h,d] */
__device__ float g_att[(size_t)M_TOTAL * DIM];     /* [b,n,h,d]                 */

/* ================================ SGEMM ==================================== */
/* C[M,N] = A[M,K] @ B[K,N] + bias[N].  M%128==0, N%128==0, K%8==0 assumed.    */
#define BM 128
#define BN 128
#define BK 8

__global__ __launch_bounds__(256, 2)
void sgemm_bias_kernel(const float* __restrict__ A, const float* __restrict__ B,
                       const float* __restrict__ bias, float* __restrict__ C,
                       int M, int N, int K)
{
    __shared__ float As[BK][BM];
    __shared__ float Bs[BK][BN];

    const int tid = threadIdx.x;
    const int bx = blockIdx.x, by = blockIdx.y;

    const float* Ab = A + (size_t)by * BM * K;
    const float* Bb = B + (size_t)bx * BN;

    const int arow = tid >> 1;            /* 0..127 */
    const int acol = (tid & 1) << 2;      /* 0 or 4 */
    const int brow = tid >> 5;            /* 0..7   */
    const int bcol = (tid & 31) << 2;     /* 0..124 */
    const int tx = tid & 15, ty = tid >> 4;

    float acc[8][8];
#pragma unroll
    for (int i = 0; i < 8; i++)
#pragma unroll
        for (int j = 0; j < 8; j++) acc[i][j] = 0.f;

    for (int k0 = 0; k0 < K; k0 += BK) {
        float4 av = *(const float4*)(Ab + (size_t)arow * K + k0 + acol);
        As[acol + 0][arow] = av.x;
        As[acol + 1][arow] = av.y;
        As[acol + 2][arow] = av.z;
        As[acol + 3][arow] = av.w;
        *(float4*)(&Bs[brow][bcol]) =
            *(const float4*)(Bb + (size_t)(k0 + brow) * N + bcol);
        __syncthreads();

#pragma unroll
        for (int kk = 0; kk < BK; kk++) {
            float ar[8], br[8];
            *(float4*)(&ar[0]) = *(const float4*)(&As[kk][ty * 4]);
            *(float4*)(&ar[4]) = *(const float4*)(&As[kk][ty * 4 + 64]);
            *(float4*)(&br[0]) = *(const float4*)(&Bs[kk][tx * 4]);
            *(float4*)(&br[4]) = *(const float4*)(&Bs[kk][tx * 4 + 64]);
#pragma unroll
            for (int i = 0; i < 8; i++)
#pragma unroll
                for (int j = 0; j < 8; j++)
                    acc[i][j] = fmaf(ar[i], br[j], acc[i][j]);
        }
        __syncthreads();
    }

#pragma unroll
    for (int ii = 0; ii < 2; ii++)
#pragma unroll
        for (int i = 0; i < 4; i++) {
            const int row = by * BM + ty * 4 + ii * 64 + i;
#pragma unroll
            for (int jj = 0; jj < 2; jj++) {
                const int col = bx * BN + tx * 4 + jj * 64;
                float4 bv = *(const float4*)(bias + col);
                float4 o;
                o.x = acc[ii * 4 + i][jj * 4 + 0] + bv.x;
                o.y = acc[ii * 4 + i][jj * 4 + 1] + bv.y;
                o.z = acc[ii * 4 + i][jj * 4 + 2] + bv.z;
                o.w = acc[ii * 4 + i][jj * 4 + 3] + bv.w;
                *(float4*)(C + (size_t)row * N + col) = o;
            }
        }
}

/* =========================== flash attention =============================== */
/* One block: 64 queries x one (b,h).  Online softmax over 13 key tiles of 64.*/
#define TQ  64
#define TK  64
#define NKT 13                       /* ceil(784/64) */
#define SPITCH 68                    /* Ss pitch: 16B aligned, staggered banks */
#define ATT_SMEM_FLOATS (HD*TQ + HD*TK + TK*HD + TK*SPITCH + 3*TQ + 4*TQ)
#define ATT_SMEM_BYTES  (ATT_SMEM_FLOATS * 4)

__global__ __launch_bounds__(256)
void attn_kernel(const float* __restrict__ qkv, float* __restrict__ out)
{
    extern __shared__ float sm[];
    float* Qs   = sm;                    /* [HD][TQ] (d-major)  */
    float* Ks   = Qs + HD * TQ;          /* [HD][TK] (d-major)  */
    float* Vs   = Ks + HD * TK;          /* [TK][HD]            */
    float* Ss   = Vs + TK * HD;          /* [TK][SPITCH] = P^T  */
    float* mrow = Ss + TK * SPITCH;      /* [TQ] running max    */
    float* lrow = mrow + TQ;             /* [TQ] running sum    */
    float* arow = lrow + TQ;             /* [TQ] rescale alpha  */
    float* red  = arow + TQ;             /* [TQ][4] partials    */

    const int tid = threadIdx.x;
    const int qt = blockIdx.x, h = blockIdx.y, b = blockIdx.z;
    const int q0 = qt * TQ;
    const int tx = tid & 15, ty = tid >> 4;
    const float scale = 0.125f;          /* 1/sqrt(64) */

    /* load + pre-scale Q tile, transposed to [d][q] */
    for (int idx = tid; idx < TQ * (HD / 4); idx += 256) {
        const int q = idx >> 4, d = (idx & 15) << 2;
        const int qg = q0 + q;
        float4 v = make_float4(0.f, 0.f, 0.f, 0.f);
        if (qg < SEQ)
            v = *(const float4*)(qkv + (size_t)(b * SEQ + qg) * QKV_N + h * HD + d);
        Qs[(d + 0) * TQ + q] = v.x * scale;
        Qs[(d + 1) * TQ + q] = v.y * scale;
        Qs[(d + 2) * TQ + q] = v.z * scale;
        Qs[(d + 3) * TQ + q] = v.w * scale;
    }
    if (tid < TQ) { mrow[tid] = -1e30f; lrow[tid] = 0.f; }

    float oacc[4][4];
#pragma unroll
    for (int i = 0; i < 4; i++)
#pragma unroll
        for (int j = 0; j < 4; j++) oacc[i][j] = 0.f;
    __syncthreads();

    for (int kt = 0; kt < NKT; kt++) {
        const int k0 = kt * TK;

        /* load K (transposed) and V tiles; zero-fill masked rows */
        for (int idx = tid; idx < TK * (HD / 4); idx += 256) {
            const int kk = idx >> 4, d = (idx & 15) << 2;
            const int kg = k0 + kk;
            float4 kv = make_float4(0.f, 0.f, 0.f, 0.f);
            float4 vv = make_float4(0.f, 0.f, 0.f, 0.f);
            if (kg < SEQ) {
                const float* base = qkv + (size_t)(b * SEQ + kg) * QKV_N + h * HD + d;
                kv = *(const float4*)(base + DIM);
                vv = *(const float4*)(base + 2 * DIM);
            }
            Ks[(d + 0) * TK + kk] = kv.x;
            Ks[(d + 1) * TK + kk] = kv.y;
            Ks[(d + 2) * TK + kk] = kv.z;
            Ks[(d + 3) * TK + kk] = kv.w;
            *(float4*)(&Vs[kk * HD + d]) = vv;
        }
        __syncthreads();

        /* S = (Q*scale) @ K^T  — thread owns 4 queries x 4 keys */
        float s[4][4];
#pragma unroll
        for (int i = 0; i < 4; i++)
#pragma unroll
            for (int j = 0; j < 4; j++) s[i][j] = 0.f;
#pragma unroll 8
        for (int d = 0; d < HD; d++) {
            float aq[4], bk[4];
            *(float4*)aq = *(const float4*)(&Qs[d * TQ + ty * 4]);
            *(float4*)bk = *(const float4*)(&Ks[d * TK + tx * 4]);
#pragma unroll
            for (int i = 0; i < 4; i++)
#pragma unroll
                for (int j = 0; j < 4; j++)
                    s[i][j] = fmaf(aq[i], bk[j], s[i][j]);
        }
        /* store transposed S^T[k][q], masking invalid keys */
#pragma unroll
        for (int j = 0; j < 4; j++) {
            const int kg = k0 + tx * 4 + j;
            float4 col;
            col.x = (kg < SEQ) ? s[0][j] : -1e30f;
            col.y = (kg < SEQ) ? s[1][j] : -1e30f;
            col.z = (kg < SEQ) ? s[2][j] : -1e30f;
            col.w = (kg < SEQ) ? s[3][j] : -1e30f;
            *(float4*)(&Ss[(tx * 4 + j) * SPITCH + ty * 4]) = col;
        }
        __syncthreads();

        /* per-query tile max (4 threads / query) */
        {
            const int q = tid >> 2, part = tid & 3;
            float mx = -1e30f;
#pragma unroll
            for (int k2 = 0; k2 < 16; k2++)
                mx = fmaxf(mx, Ss[(part * 16 + k2) * SPITCH + q]);
            red[q * 4 + part] = mx;
        }
        __syncthreads();
        if (tid < TQ) {
            const float mx = fmaxf(fmaxf(red[tid * 4 + 0], red[tid * 4 + 1]),
                                   fmaxf(red[tid * 4 + 2], red[tid * 4 + 3]));
            const float mo = mrow[tid];
            const float mn = fmaxf(mo, mx);
            const float al = __expf(mo - mn);
            arow[tid] = al; mrow[tid] = mn; lrow[tid] *= al;
        }
        __syncthreads();

        /* rescale accumulators */
#pragma unroll
        for (int i = 0; i < 4; i++) {
            const float al = arow[ty * 4 + i];
#pragma unroll
            for (int j = 0; j < 4; j++) oacc[i][j] *= al;
        }
        /* exponentiate in place + partial sums */
        {
            const int q = tid >> 2, part = tid & 3;
            const float mn = mrow[q];
            float sum = 0.f;
#pragma unroll
            for (int k2 = 0; k2 < 16; k2++) {
                const int kk = part * 16 + k2;
                const float p = __expf(Ss[kk * SPITCH + q] - mn);
                Ss[kk * SPITCH + q] = p;
                sum += p;
            }
            red[q * 4 + part] = sum;
        }
        __syncthreads();
        if (tid < TQ)
            lrow[tid] += red[tid * 4 + 0] + red[tid * 4 + 1] +
                         red[tid * 4 + 2] + red[tid * 4 + 3];

        /* O += P @ V */
#pragma unroll 8
        for (int kk = 0; kk < TK; kk++) {
            float p[4], v[4];
            *(float4*)p = *(const float4*)(&Ss[kk * SPITCH + ty * 4]);
            *(float4*)v = *(const float4*)(&Vs[kk * HD + tx * 4]);
#pragma unroll
            for (int i = 0; i < 4; i++)
#pragma unroll
                for (int j = 0; j < 4; j++)
                    oacc[i][j] = fmaf(p[i], v[j], oacc[i][j]);
        }
        __syncthreads();
    }

    /* normalize + write [b,n,h,d] */
#pragma unroll
    for (int i = 0; i < 4; i++) {
        const int q = ty * 4 + i;
        const int qg = q0 + q;
        if (qg < SEQ) {
            const float inv = 1.f / lrow[q];
            float4 o;
            o.x = oacc[i][0] * inv;
            o.y = oacc[i][1] * inv;
            o.z = oacc[i][2] * inv;
            o.w = oacc[i][3] * inv;
            *(float4*)(out + (size_t)(b * SEQ + qg) * DIM + h * HD + tx * 4) = o;
        }
    }
}

/* ================================ launch =================================== */
extern "C" void kernel_launch(void* const* d_in, const int* in_sizes, int n_in,
                              void* d_out, int out_size)
{
    const float* x    = (const float*)d_in[0];
    const float* Wqkv = (const float*)d_in[1];
    const float* bqkv = (const float*)d_in[2];
    const float* Wo   = (const float*)d_in[3];
    const float* bo   = (const float*)d_in[4];
    float* out = (float*)d_out;

    float *qkv, *att;
    cudaGetSymbolAddress((void**)&qkv, g_qkv);
    cudaGetSymbolAddress((void**)&att, g_att);

    /* 1) QKV projection: [12544,768] @ [768,2304] + bqkv */
    dim3 g1(QKV_N / BN, M_TOTAL / BM);
    sgemm_bias_kernel<<<g1, 256>>>(x, Wqkv, bqkv, qkv, M_TOTAL, QKV_N, DIM);

    /* 2) fused flash attention */
    cudaFuncSetAttribute(attn_kernel, cudaFuncAttributeMaxDynamicSharedMemorySize,
                         ATT_SMEM_BYTES);
    attn_kernel<<<dim3(NKT, NH, BATCH), 256, ATT_SMEM_BYTES>>>(qkv, att);

    /* 3) output projection: [12544,768] @ [768,768] + bo */
    dim3 g3(DIM / BN, M_TOTAL / BM);
    sgemm_bias_kernel<<<g3, 256>>>(att, Wo, bo, out, M_TOTAL, DIM, DIM);
}

// round 3
// speedup vs baseline: 1.2073x; 1.2073x over previous
#include <cuda_runtime.h>
#include <cuda_bf16.h>
#include <cstdint>

#define DIM    768
#define NH     12
#define HD     64
#define BATCH  16
#define SEQ    784
#define M_TOTAL (BATCH * SEQ)      /* 12544 */
#define QKV_N   (3 * DIM)          /* 2304  */

/* ---------------- scratch (allocation-free rule: __device__ globals) ------- */
__device__ float g_qkv[(size_t)M_TOTAL * QKV_N];   /* [M,3*DIM] fp32 */
__device__ float g_att[(size_t)M_TOTAL * DIM];     /* [M,DIM]   fp32 */
__device__ __nv_bfloat16 g_xh[(size_t)M_TOTAL * DIM];
__device__ __nv_bfloat16 g_xl[(size_t)M_TOTAL * DIM];
__device__ __nv_bfloat16 g_ath[(size_t)M_TOTAL * DIM];
__device__ __nv_bfloat16 g_atl[(size_t)M_TOTAL * DIM];
__device__ __nv_bfloat16 g_wqh[(size_t)QKV_N * DIM];   /* W^T [N,K] */
__device__ __nv_bfloat16 g_wql[(size_t)QKV_N * DIM];
__device__ __nv_bfloat16 g_woh[(size_t)DIM * DIM];
__device__ __nv_bfloat16 g_wol[(size_t)DIM * DIM];

/* ========================= PTX helpers (compute_80+) ======================= */
__device__ __forceinline__ uint32_t smem_u32(const void* p) {
    uint32_t a;
    asm("{ .reg .u64 t; cvta.to.shared.u64 t, %1; cvt.u32.u64 %0, t; }"
        : "=r"(a) : "l"(p));
    return a;
}
__device__ __forceinline__ void cp16(uint32_t s, const void* g) {
    asm volatile("cp.async.cg.shared.global [%0], [%1], 16;"
                 :: "r"(s), "l"(g) : "memory");
}
__device__ __forceinline__ void ldmx4(uint32_t* r, const void* p) {
    uint32_t a = smem_u32(p);
    asm volatile("ldmatrix.sync.aligned.m8n8.x4.shared.b16 {%0,%1,%2,%3}, [%4];"
                 : "=r"(r[0]), "=r"(r[1]), "=r"(r[2]), "=r"(r[3]) : "r"(a));
}
__device__ __forceinline__ void mma16816(float* c, const uint32_t* a,
                                         uint32_t b0, uint32_t b1) {
    asm volatile(
        "mma.sync.aligned.m16n8k16.row.col.f32.bf16.bf16.f32 "
        "{%0,%1,%2,%3},{%4,%5,%6,%7},{%8,%9},{%0,%1,%2,%3};"
        : "+f"(c[0]), "+f"(c[1]), "+f"(c[2]), "+f"(c[3])
        : "r"(a[0]), "r"(a[1]), "r"(a[2]), "r"(a[3]), "r"(b0), "r"(b1));
}

/* ======================= split / transpose kernels ========================= */
__global__ __launch_bounds__(256)
void split_kernel(const float4* __restrict__ in, __nv_bfloat162* __restrict__ hi,
                  __nv_bfloat162* __restrict__ lo, int n4)
{
    int i = blockIdx.x * 256 + threadIdx.x;
    if (i >= n4) return;
    float4 v = in[i];
    __nv_bfloat16 hx = __float2bfloat16(v.x), hy = __float2bfloat16(v.y);
    __nv_bfloat16 hz = __float2bfloat16(v.z), hw = __float2bfloat16(v.w);
    hi[2 * i + 0] = __halves2bfloat162(hx, hy);
    hi[2 * i + 1] = __halves2bfloat162(hz, hw);
    lo[2 * i + 0] = __halves2bfloat162(__float2bfloat16(v.x - __bfloat162float(hx)),
                                       __float2bfloat16(v.y - __bfloat162float(hy)));
    lo[2 * i + 1] = __halves2bfloat162(__float2bfloat16(v.z - __bfloat162float(hz)),
                                       __float2bfloat16(v.w - __bfloat162float(hw)));
}

/* in [K,N] fp32 -> hi/lo [N,K] bf16 */
__global__ __launch_bounds__(256)
void transpose_split_kernel(const float* __restrict__ in, __nv_bfloat16* __restrict__ hi,
                            __nv_bfloat16* __restrict__ lo, int K, int N)
{
    __shared__ float t[32][33];
    const int k0 = blockIdx.y * 32, n0 = blockIdx.x * 32;
    const int tx = threadIdx.x & 31, ty = threadIdx.x >> 5;
#pragma unroll
    for (int i = 0; i < 32; i += 8)
        t[ty + i][tx] = in[(size_t)(k0 + ty + i) * N + n0 + tx];
    __syncthreads();
#pragma unroll
    for (int i = 0; i < 32; i += 8) {
        const int n = n0 + ty + i, k = k0 + tx;
        const float v = t[tx][ty + i];
        const __nv_bfloat16 h = __float2bfloat16(v);
        hi[(size_t)n * K + k] = h;
        lo[(size_t)n * K + k] = __float2bfloat16(v - __bfloat162float(h));
    }
}

/* ===================== mma.sync bf16 split-GEMM kernel ===================== */
/* C[128,128] = sum_{p in {AhBh,AhBl,AlBh}} A_p[M,768] * B_p[N,768]^T + bias   */
#define BKH   32                     /* K halves per iteration */
#define NCHP  (DIM / BKH)            /* 24 iters per phase     */
#define NITER (3 * NCHP)             /* 72 total               */
#define PITCH 40                     /* smem row pitch, halves (80B: xbar-clean)*/

__global__ __launch_bounds__(256)
void mma_gemm_kernel(const __nv_bfloat16* __restrict__ Ah, const __nv_bfloat16* __restrict__ Al,
                     const __nv_bfloat16* __restrict__ Bh, const __nv_bfloat16* __restrict__ Bl,
                     const float* __restrict__ bias, float* __restrict__ C, int Ntot)
{
    __shared__ __nv_bfloat16 As[2][128 * PITCH];
    __shared__ __nv_bfloat16 Bs[2][128 * PITCH];

    const int tid = threadIdx.x;
    const int wid = tid >> 5, lane = tid & 31;
    const int wm = wid & 3, wn = wid >> 2;         /* 4 x 2 warp grid */
    const int bx = blockIdx.x, by = blockIdx.y;

    const __nv_bfloat16* Asel[3] = { Ah, Ah, Al };
    const __nv_bfloat16* Bsel[3] = { Bh, Bl, Bh };

    /* per-thread gmem/smem chunk coords: 2 x 16B chunks each for A and B */
    const int r0c = (tid * 2) >> 2, c0c = (tid * 2) & 3;
    const int r1c = (tid * 2 + 1) >> 2, c1c = (tid * 2 + 1) & 3;

    auto load_tile = [&](int it, int buf) {
        const int p = it / NCHP, kc = it % NCHP;
        const __nv_bfloat16* Ap = Asel[p] + (size_t)(by * 128) * DIM + kc * BKH;
        const __nv_bfloat16* Bp = Bsel[p] + (size_t)(bx * 128) * DIM + kc * BKH;
        uint32_t sa = smem_u32(&As[buf][0]);
        uint32_t sb = smem_u32(&Bs[buf][0]);
        cp16(sa + (r0c * PITCH + c0c * 8) * 2, Ap + (size_t)r0c * DIM + c0c * 8);
        cp16(sa + (r1c * PITCH + c1c * 8) * 2, Ap + (size_t)r1c * DIM + c1c * 8);
        cp16(sb + (r0c * PITCH + c0c * 8) * 2, Bp + (size_t)r0c * DIM + c0c * 8);
        cp16(sb + (r1c * PITCH + c1c * 8) * 2, Bp + (size_t)r1c * DIM + c1c * 8);
        asm volatile("cp.async.commit_group;" ::: "memory");
    };

    float acc[2][8][4];
#pragma unroll
    for (int mf = 0; mf < 2; mf++)
#pragma unroll
        for (int nf = 0; nf < 8; nf++)
#pragma unroll
            for (int q = 0; q < 4; q++) acc[mf][nf][q] = 0.f;

    load_tile(0, 0);

    int cb = 0;
    for (int it = 0; it < NITER; it++) {
        if (it + 1 < NITER) {
            load_tile(it + 1, cb ^ 1);
            asm volatile("cp.async.wait_group 1;" ::: "memory");
        } else {
            asm volatile("cp.async.wait_group 0;" ::: "memory");
        }
        __syncthreads();

        const __nv_bfloat16* Ab = &As[cb][0];
        const __nv_bfloat16* Bb = &Bs[cb][0];
#pragma unroll
        for (int ks = 0; ks < 2; ks++) {
            uint32_t ar[2][4];
#pragma unroll
            for (int mf = 0; mf < 2; mf++)
                ldmx4(ar[mf],
                      Ab + (wm * 32 + mf * 16 + (lane & 15)) * PITCH
                         + ks * 16 + (lane >> 4) * 8);
            uint32_t br[4][4];
#pragma unroll
            for (int np = 0; np < 4; np++)
                ldmx4(br[np],
                      Bb + (wn * 64 + np * 16 + ((lane >> 4) << 3) + (lane & 7)) * PITCH
                         + ks * 16 + (((lane >> 3) & 1) << 3));
#pragma unroll
            for (int mf = 0; mf < 2; mf++)
#pragma unroll
                for (int nf = 0; nf < 8; nf++)
                    mma16816(acc[mf][nf], ar[mf],
                             br[nf >> 1][(nf & 1) * 2],
                             br[nf >> 1][(nf & 1) * 2 + 1]);
        }
        __syncthreads();
        cb ^= 1;
    }

    /* epilogue: fragment layout c0,c1: (row, col..col+1); c2,c3: row+8 */
    const int rbase = by * 128 + wm * 32;
    const int cbase = bx * 128 + wn * 64;
#pragma unroll
    for (int mf = 0; mf < 2; mf++) {
        const int row = rbase + mf * 16 + (lane >> 2);
#pragma unroll
        for (int nf = 0; nf < 8; nf++) {
            const int col = cbase + nf * 8 + (lane & 3) * 2;
            const float2 bv = *(const float2*)(bias + col);
            float2 o0, o1;
            o0.x = acc[mf][nf][0] + bv.x;  o0.y = acc[mf][nf][1] + bv.y;
            o1.x = acc[mf][nf][2] + bv.x;  o1.y = acc[mf][nf][3] + bv.y;
            *(float2*)(C + (size_t)row * Ntot + col) = o0;
            *(float2*)(C + (size_t)(row + 8) * Ntot + col) = o1;
        }
    }
}

/* =========================== flash attention =============================== */
#define TQ  64
#define TK  64
#define NKT 13
#define SPITCH 68
#define ATT_SMEM_FLOATS (HD*TQ + HD*TK + TK*HD + TK*SPITCH + 3*TQ + 4*TQ)
#define ATT_SMEM_BYTES  (ATT_SMEM_FLOATS * 4)

__global__ __launch_bounds__(256)
void attn_kernel(const float* __restrict__ qkv, float* __restrict__ out)
{
    extern __shared__ float sm[];
    float* Qs   = sm;
    float* Ks   = Qs + HD * TQ;
    float* Vs   = Ks + HD * TK;
    float* Ss   = Vs + TK * HD;
    float* mrow = Ss + TK * SPITCH;
    float* lrow = mrow + TQ;
    float* arow = lrow + TQ;
    float* red  = arow + TQ;

    const int tid = threadIdx.x;
    const int qt = blockIdx.x, h = blockIdx.y, b = blockIdx.z;
    const int q0 = qt * TQ;
    const int tx = tid & 15, ty = tid >> 4;
    const float scale = 0.125f;

    for (int idx = tid; idx < TQ * (HD / 4); idx += 256) {
        const int q = idx >> 4, d = (idx & 15) << 2;
        const int qg = q0 + q;
        float4 v = make_float4(0.f, 0.f, 0.f, 0.f);
        if (qg < SEQ)
            v = *(const float4*)(qkv + (size_t)(b * SEQ + qg) * QKV_N + h * HD + d);
        Qs[(d + 0) * TQ + q] = v.x * scale;
        Qs[(d + 1) * TQ + q] = v.y * scale;
        Qs[(d + 2) * TQ + q] = v.z * scale;
        Qs[(d + 3) * TQ + q] = v.w * scale;
    }
    if (tid < TQ) { mrow[tid] = -1e30f; lrow[tid] = 0.f; }

    float oacc[4][4];
#pragma unroll
    for (int i = 0; i < 4; i++)
#pragma unroll
        for (int j = 0; j < 4; j++) oacc[i][j] = 0.f;
    __syncthreads();

    for (int kt = 0; kt < NKT; kt++) {
        const int k0 = kt * TK;
        for (int idx = tid; idx < TK * (HD / 4); idx += 256) {
            const int kk = idx >> 4, d = (idx & 15) << 2;
            const int kg = k0 + kk;
            float4 kv = make_float4(0.f, 0.f, 0.f, 0.f);
            float4 vv = make_float4(0.f, 0.f, 0.f, 0.f);
            if (kg < SEQ) {
                const float* base = qkv + (size_t)(b * SEQ + kg) * QKV_N + h * HD + d;
                kv = *(const float4*)(base + DIM);
                vv = *(const float4*)(base + 2 * DIM);
            }
            Ks[(d + 0) * TK + kk] = kv.x;
            Ks[(d + 1) * TK + kk] = kv.y;
            Ks[(d + 2) * TK + kk] = kv.z;
            Ks[(d + 3) * TK + kk] = kv.w;
            *(float4*)(&Vs[kk * HD + d]) = vv;
        }
        __syncthreads();

        float s[4][4];
#pragma unroll
        for (int i = 0; i < 4; i++)
#pragma unroll
            for (int j = 0; j < 4; j++) s[i][j] = 0.f;
#pragma unroll 8
        for (int d = 0; d < HD; d++) {
            float aq[4], bk[4];
            *(float4*)aq = *(const float4*)(&Qs[d * TQ + ty * 4]);
            *(float4*)bk = *(const float4*)(&Ks[d * TK + tx * 4]);
#pragma unroll
            for (int i = 0; i < 4; i++)
#pragma unroll
                for (int j = 0; j < 4; j++)
                    s[i][j] = fmaf(aq[i], bk[j], s[i][j]);
        }
#pragma unroll
        for (int j = 0; j < 4; j++) {
            const int kg = k0 + tx * 4 + j;
            float4 col;
            col.x = (kg < SEQ) ? s[0][j] : -1e30f;
            col.y = (kg < SEQ) ? s[1][j] : -1e30f;
            col.z = (kg < SEQ) ? s[2][j] : -1e30f;
            col.w = (kg < SEQ) ? s[3][j] : -1e30f;
            *(float4*)(&Ss[(tx * 4 + j) * SPITCH + ty * 4]) = col;
        }
        __syncthreads();

        {
            const int q = tid >> 2, part = tid & 3;
            float mx = -1e30f;
#pragma unroll
            for (int k2 = 0; k2 < 16; k2++)
                mx = fmaxf(mx, Ss[(part * 16 + k2) * SPITCH + q]);
            red[q * 4 + part] = mx;
        }
        __syncthreads();
        if (tid < TQ) {
            const float mx = fmaxf(fmaxf(red[tid * 4 + 0], red[tid * 4 + 1]),
                                   fmaxf(red[tid * 4 + 2], red[tid * 4 + 3]));
            const float mo = mrow[tid];
            const float mn = fmaxf(mo, mx);
            const float al = __expf(mo - mn);
            arow[tid] = al; mrow[tid] = mn; lrow[tid] *= al;
        }
        __syncthreads();

#pragma unroll
        for (int i = 0; i < 4; i++) {
            const float al = arow[ty * 4 + i];
#pragma unroll
            for (int j = 0; j < 4; j++) oacc[i][j] *= al;
        }
        {
            const int q = tid >> 2, part = tid & 3;
            const float mn = mrow[q];
            float sum = 0.f;
#pragma unroll
            for (int k2 = 0; k2 < 16; k2++) {
                const int kk = part * 16 + k2;
                const float p = __expf(Ss[kk * SPITCH + q] - mn);
                Ss[kk * SPITCH + q] = p;
                sum += p;
            }
            red[q * 4 + part] = sum;
        }
        __syncthreads();
        if (tid < TQ)
            lrow[tid] += red[tid * 4 + 0] + red[tid * 4 + 1] +
                         red[tid * 4 + 2] + red[tid * 4 + 3];

#pragma unroll 8
        for (int kk = 0; kk < TK; kk++) {
            float p[4], v[4];
            *(float4*)p = *(const float4*)(&Ss[kk * SPITCH + ty * 4]);
            *(float4*)v = *(const float4*)(&Vs[kk * HD + tx * 4]);
#pragma unroll
            for (int i = 0; i < 4; i++)
#pragma unroll
                for (int j = 0; j < 4; j++)
                    oacc[i][j] = fmaf(p[i], v[j], oacc[i][j]);
        }
        __syncthreads();
    }

#pragma unroll
    for (int i = 0; i < 4; i++) {
        const int q = ty * 4 + i;
        const int qg = q0 + q;
        if (qg < SEQ) {
            const float inv = 1.f / lrow[q];
            float4 o;
            o.x = oacc[i][0] * inv;
            o.y = oacc[i][1] * inv;
            o.z = oacc[i][2] * inv;
            o.w = oacc[i][3] * inv;
            *(float4*)(out + (size_t)(b * SEQ + qg) * DIM + h * HD + tx * 4) = o;
        }
    }
}

/* ================================ launch =================================== */
extern "C" void kernel_launch(void* const* d_in, const int* in_sizes, int n_in,
                              void* d_out, int out_size)
{
    const float* x    = (const float*)d_in[0];
    const float* Wqkv = (const float*)d_in[1];
    const float* bqkv = (const float*)d_in[2];
    const float* Wo   = (const float*)d_in[3];
    const float* bo   = (const float*)d_in[4];
    float* out = (float*)d_out;

    float *qkv, *att;
    __nv_bfloat16 *xh, *xl, *ath, *atl, *wqh, *wql, *woh, *wol;
    cudaGetSymbolAddress((void**)&qkv, g_qkv);
    cudaGetSymbolAddress((void**)&att, g_att);
    cudaGetSymbolAddress((void**)&xh,  g_xh);
    cudaGetSymbolAddress((void**)&xl,  g_xl);
    cudaGetSymbolAddress((void**)&ath, g_ath);
    cudaGetSymbolAddress((void**)&atl, g_atl);
    cudaGetSymbolAddress((void**)&wqh, g_wqh);
    cudaGetSymbolAddress((void**)&wql, g_wql);
    cudaGetSymbolAddress((void**)&woh, g_woh);
    cudaGetSymbolAddress((void**)&wol, g_wol);

    cudaFuncSetAttribute(attn_kernel, cudaFuncAttributeMaxDynamicSharedMemorySize,
                         ATT_SMEM_BYTES);

    /* split x into bf16 hi/lo */
    {
        const int n4 = M_TOTAL * DIM / 4;
        split_kernel<<<(n4 + 255) / 256, 256>>>((const float4*)x,
                                                (__nv_bfloat162*)xh,
                                                (__nv_bfloat162*)xl, n4);
    }
    /* transpose+split weights */
    transpose_split_kernel<<<dim3(QKV_N / 32, DIM / 32), 256>>>(Wqkv, wqh, wql, DIM, QKV_N);
    transpose_split_kernel<<<dim3(DIM / 32, DIM / 32), 256>>>(Wo, woh, wol, DIM, DIM);

    /* 1) QKV projection via mma.sync split-GEMM */
    mma_gemm_kernel<<<dim3(QKV_N / 128, M_TOTAL / 128), 256>>>(
        xh, xl, wqh, wql, bqkv, qkv, QKV_N);

    /* 2) fused flash attention (fp32) */
    attn_kernel<<<dim3(NKT, NH, BATCH), 256, ATT_SMEM_BYTES>>>(qkv, att);

    /* 3) split attention output, then output projection */
    {
        const int n4 = M_TOTAL * DIM / 4;
        split_kernel<<<(n4 + 255) / 256, 256>>>((const float4*)att,
                                                (__nv_bfloat162*)ath,
                                                (__nv_bfloat162*)atl, n4);
    }
    mma_gemm_kernel<<<dim3(DIM / 128, M_TOTAL / 128), 256>>>(
        ath, atl, woh, wol, bo, out, DIM);
}

// round 4
// speedup vs baseline: 2.1092x; 1.7470x over previous
#include <cuda_runtime.h>
#include <cuda_bf16.h>
#include <cstdint>

#define DIM    768
#define NH     12
#define HD     64
#define BATCH  16
#define SEQ    784
#define M_TOTAL (BATCH * SEQ)      /* 12544 */
#define QKV_N   (3 * DIM)          /* 2304  */

/* ---------------- scratch (allocation-free rule: __device__ globals) ------- */
__device__ float g_qkv[(size_t)M_TOTAL * QKV_N];   /* [M,3*DIM] fp32 */
__device__ float g_att[(size_t)M_TOTAL * DIM];     /* [M,DIM]   fp32 */
__device__ __nv_bfloat16 g_xh[(size_t)M_TOTAL * DIM];
__device__ __nv_bfloat16 g_xl[(size_t)M_TOTAL * DIM];
__device__ __nv_bfloat16 g_ath[(size_t)M_TOTAL * DIM];
__device__ __nv_bfloat16 g_atl[(size_t)M_TOTAL * DIM];
__device__ __nv_bfloat16 g_wqh[(size_t)QKV_N * DIM];   /* W^T [N,K] */
__device__ __nv_bfloat16 g_wql[(size_t)QKV_N * DIM];
__device__ __nv_bfloat16 g_woh[(size_t)DIM * DIM];
__device__ __nv_bfloat16 g_wol[(size_t)DIM * DIM];

/* ========================= PTX helpers (compute_80+) ======================= */
__device__ __forceinline__ uint32_t smem_u32(const void* p) {
    uint32_t a;
    asm("{ .reg .u64 t; cvta.to.shared.u64 t, %1; cvt.u32.u64 %0, t; }"
        : "=r"(a) : "l"(p));
    return a;
}
__device__ __forceinline__ void cp16(uint32_t s, const void* g) {
    asm volatile("cp.async.cg.shared.global [%0], [%1], 16;"
                 :: "r"(s), "l"(g) : "memory");
}
__device__ __forceinline__ void ldmx4(uint32_t* r, const void* p) {
    uint32_t a = smem_u32(p);
    asm volatile("ldmatrix.sync.aligned.m8n8.x4.shared.b16 {%0,%1,%2,%3}, [%4];"
                 : "=r"(r[0]), "=r"(r[1]), "=r"(r[2]), "=r"(r[3]) : "r"(a));
}
__device__ __forceinline__ void ldmx4t(uint32_t* r, const void* p) {
    uint32_t a = smem_u32(p);
    asm volatile("ldmatrix.sync.aligned.m8n8.x4.trans.shared.b16 {%0,%1,%2,%3}, [%4];"
                 : "=r"(r[0]), "=r"(r[1]), "=r"(r[2]), "=r"(r[3]) : "r"(a));
}
__device__ __forceinline__ void mma16816(float* c, const uint32_t* a,
                                         uint32_t b0, uint32_t b1) {
    asm volatile(
        "mma.sync.aligned.m16n8k16.row.col.f32.bf16.bf16.f32 "
        "{%0,%1,%2,%3},{%4,%5,%6,%7},{%8,%9},{%0,%1,%2,%3};"
        : "+f"(c[0]), "+f"(c[1]), "+f"(c[2]), "+f"(c[3])
        : "r"(a[0]), "r"(a[1]), "r"(a[2]), "r"(a[3]), "r"(b0), "r"(b1));
}
__device__ __forceinline__ uint32_t packbf(float x, float y) {
    __nv_bfloat162 t = __halves2bfloat162(__float2bfloat16(x), __float2bfloat16(y));
    return *reinterpret_cast<uint32_t*>(&t);
}
__device__ __forceinline__ float bflo(float x) {          /* round-to-bf16 value */
    return __bfloat162float(__float2bfloat16(x));
}

/* ======================= split / transpose kernels ========================= */
__global__ __launch_bounds__(256)
void split_kernel(const float4* __restrict__ in, __nv_bfloat162* __restrict__ hi,
                  __nv_bfloat162* __restrict__ lo, int n4)
{
    int i = blockIdx.x * 256 + threadIdx.x;
    if (i >= n4) return;
    float4 v = in[i];
    __nv_bfloat16 hx = __float2bfloat16(v.x), hy = __float2bfloat16(v.y);
    __nv_bfloat16 hz = __float2bfloat16(v.z), hw = __float2bfloat16(v.w);
    hi[2 * i + 0] = __halves2bfloat162(hx, hy);
    hi[2 * i + 1] = __halves2bfloat162(hz, hw);
    lo[2 * i + 0] = __halves2bfloat162(__float2bfloat16(v.x - __bfloat162float(hx)),
                                       __float2bfloat16(v.y - __bfloat162float(hy)));
    lo[2 * i + 1] = __halves2bfloat162(__float2bfloat16(v.z - __bfloat162float(hz)),
                                       __float2bfloat16(v.w - __bfloat162float(hw)));
}

/* in [K,N] fp32 -> hi/lo [N,K] bf16 */
__global__ __launch_bounds__(256)
void transpose_split_kernel(const float* __restrict__ in, __nv_bfloat16* __restrict__ hi,
                            __nv_bfloat16* __restrict__ lo, int K, int N)
{
    __shared__ float t[32][33];
    const int k0 = blockIdx.y * 32, n0 = blockIdx.x * 32;
    const int tx = threadIdx.x & 31, ty = threadIdx.x >> 5;
#pragma unroll
    for (int i = 0; i < 32; i += 8)
        t[ty + i][tx] = in[(size_t)(k0 + ty + i) * N + n0 + tx];
    __syncthreads();
#pragma unroll
    for (int i = 0; i < 32; i += 8) {
        const int n = n0 + ty + i, k = k0 + tx;
        const float v = t[tx][ty + i];
        const __nv_bfloat16 h = __float2bfloat16(v);
        hi[(size_t)n * K + k] = h;
        lo[(size_t)n * K + k] = __float2bfloat16(v - __bfloat162float(h));
    }
}

/* ===================== mma.sync bf16 split-GEMM kernel ===================== */
#define BKH   32
#define NCHP  (DIM / BKH)
#define NITER (3 * NCHP)
#define PITCH 40

__global__ __launch_bounds__(256)
void mma_gemm_kernel(const __nv_bfloat16* __restrict__ Ah, const __nv_bfloat16* __restrict__ Al,
                     const __nv_bfloat16* __restrict__ Bh, const __nv_bfloat16* __restrict__ Bl,
                     const float* __restrict__ bias, float* __restrict__ C, int Ntot)
{
    __shared__ __nv_bfloat16 As[2][128 * PITCH];
    __shared__ __nv_bfloat16 Bs[2][128 * PITCH];

    const int tid = threadIdx.x;
    const int wid = tid >> 5, lane = tid & 31;
    const int wm = wid & 3, wn = wid >> 2;
    const int bx = blockIdx.x, by = blockIdx.y;

    const __nv_bfloat16* Asel[3] = { Ah, Ah, Al };
    const __nv_bfloat16* Bsel[3] = { Bh, Bl, Bh };

    const int r0c = (tid * 2) >> 2, c0c = (tid * 2) & 3;
    const int r1c = (tid * 2 + 1) >> 2, c1c = (tid * 2 + 1) & 3;

    auto load_tile = [&](int it, int buf) {
        const int p = it / NCHP, kc = it % NCHP;
        const __nv_bfloat16* Ap = Asel[p] + (size_t)(by * 128) * DIM + kc * BKH;
        const __nv_bfloat16* Bp = Bsel[p] + (size_t)(bx * 128) * DIM + kc * BKH;
        uint32_t sa = smem_u32(&As[buf][0]);
        uint32_t sb = smem_u32(&Bs[buf][0]);
        cp16(sa + (r0c * PITCH + c0c * 8) * 2, Ap + (size_t)r0c * DIM + c0c * 8);
        cp16(sa + (r1c * PITCH + c1c * 8) * 2, Ap + (size_t)r1c * DIM + c1c * 8);
        cp16(sb + (r0c * PITCH + c0c * 8) * 2, Bp + (size_t)r0c * DIM + c0c * 8);
        cp16(sb + (r1c * PITCH + c1c * 8) * 2, Bp + (size_t)r1c * DIM + c1c * 8);
        asm volatile("cp.async.commit_group;" ::: "memory");
    };

    float acc[2][8][4];
#pragma unroll
    for (int mf = 0; mf < 2; mf++)
#pragma unroll
        for (int nf = 0; nf < 8; nf++)
#pragma unroll
            for (int q = 0; q < 4; q++) acc[mf][nf][q] = 0.f;

    load_tile(0, 0);

    int cb = 0;
    for (int it = 0; it < NITER; it++) {
        if (it + 1 < NITER) {
            load_tile(it + 1, cb ^ 1);
            asm volatile("cp.async.wait_group 1;" ::: "memory");
        } else {
            asm volatile("cp.async.wait_group 0;" ::: "memory");
        }
        __syncthreads();

        const __nv_bfloat16* Ab = &As[cb][0];
        const __nv_bfloat16* Bb = &Bs[cb][0];
#pragma unroll
        for (int ks = 0; ks < 2; ks++) {
            uint32_t ar[2][4];
#pragma unroll
            for (int mf = 0; mf < 2; mf++)
                ldmx4(ar[mf],
                      Ab + (wm * 32 + mf * 16 + (lane & 15)) * PITCH
                         + ks * 16 + (lane >> 4) * 8);
            uint32_t br[4][4];
#pragma unroll
            for (int np = 0; np < 4; np++)
                ldmx4(br[np],
                      Bb + (wn * 64 + np * 16 + ((lane >> 4) << 3) + (lane & 7)) * PITCH
                         + ks * 16 + (((lane >> 3) & 1) << 3));
#pragma unroll
            for (int mf = 0; mf < 2; mf++)
#pragma unroll
                for (int nf = 0; nf < 8; nf++)
                    mma16816(acc[mf][nf], ar[mf],
                             br[nf >> 1][(nf & 1) * 2],
                             br[nf >> 1][(nf & 1) * 2 + 1]);
        }
        __syncthreads();
        cb ^= 1;
    }

    const int rbase = by * 128 + wm * 32;
    const int cbase = bx * 128 + wn * 64;
#pragma unroll
    for (int mf = 0; mf < 2; mf++) {
        const int row = rbase + mf * 16 + (lane >> 2);
#pragma unroll
        for (int nf = 0; nf < 8; nf++) {
            const int col = cbase + nf * 8 + (lane & 3) * 2;
            const float2 bv = *(const float2*)(bias + col);
            float2 o0, o1;
            o0.x = acc[mf][nf][0] + bv.x;  o0.y = acc[mf][nf][1] + bv.y;
            o1.x = acc[mf][nf][2] + bv.x;  o1.y = acc[mf][nf][3] + bv.y;
            *(float2*)(C + (size_t)row * Ntot + col) = o0;
            *(float2*)(C + (size_t)(row + 8) * Ntot + col) = o1;
        }
    }
}

/* ====================== mma.sync split flash attention ===================== */
/* CTA: 256 thr / 8 warps; TQ=128 (16 rows/warp); TK=64; 13 key tiles.        */
#define ATQ  128
#define ATK  64
#define NQT  7                        /* ceil(784/128) */
#define ANKT 13                       /* ceil(784/64)  */
#define KP   72                       /* smem pitch in halves (144B rows)     */
#define TILE_HALVES (ATK * KP)        /* 4608 halves = 9216 B per array       */
#define ATT_SMEM (2 * 4 * TILE_HALVES * 2)   /* 2 bufs x {kh,kl,vh,vl} = 73728B */

__global__ __launch_bounds__(256)
void attn_mma_kernel(const float* __restrict__ qkv, float* __restrict__ out)
{
    extern __shared__ __nv_bfloat16 sh[];
    const int tid = threadIdx.x, wid = tid >> 5, lane = tid & 31;
    const int qt = blockIdx.x, h = blockIdx.y, b = blockIdx.z;
    const int q0 = qt * ATQ;

    /* smem sub-arrays */
    auto KH = [&](int buf) { return sh + (size_t)buf * 4 * TILE_HALVES; };
    auto KL = [&](int buf) { return KH(buf) + TILE_HALVES; };
    auto VH = [&](int buf) { return KH(buf) + 2 * TILE_HALVES; };
    auto VL = [&](int buf) { return KH(buf) + 3 * TILE_HALVES; };

    /* ---- Q fragments (persistent, pre-scaled, hi/lo split) ---- */
    uint32_t qfh[4][4], qfl[4][4];
#pragma unroll
    for (int kb = 0; kb < 4; kb++)
#pragma unroll
        for (int i = 0; i < 4; i++) {
            const int row = ((i & 1) << 3) + (lane >> 2);
            const int kofs = kb * 16 + ((i >> 1) << 3) + ((lane & 3) << 1);
            int qg = q0 + wid * 16 + row;
            if (qg > SEQ - 1) qg = SEQ - 1;
            const float2 qv = *(const float2*)(qkv + (size_t)(b * SEQ + qg) * QKV_N
                                               + h * HD + kofs);
            const float sx = qv.x * 0.125f, sy = qv.y * 0.125f;
            const float hx = bflo(sx), hy = bflo(sy);
            qfh[kb][i] = packbf(hx, hy);
            qfl[kb][i] = packbf(sx - hx, sy - hy);
        }

    /* per-thread K/V load mapping: key = tid>>2 (0..63), db = tid&3 (d-block) */
    const int lkey = tid >> 2, ldb = tid & 3;
    float4 kreg[4], vreg[4];

    auto load_regs = [&](int kt) {
        int kg = kt * ATK + lkey;
        if (kg > SEQ - 1) kg = SEQ - 1;
        const float* base = qkv + (size_t)(b * SEQ + kg) * QKV_N + h * HD + ldb * 16;
#pragma unroll
        for (int j = 0; j < 4; j++) {
            kreg[j] = *(const float4*)(base + DIM + j * 4);
            vreg[j] = *(const float4*)(base + 2 * DIM + j * 4);
        }
    };
    auto store_tile = [&](int buf) {
        __nv_bfloat16* kh = KH(buf); __nv_bfloat16* kl = KL(buf);
        __nv_bfloat16* vh = VH(buf); __nv_bfloat16* vl = VL(buf);
        const int o = lkey * KP + ldb * 16;
#pragma unroll
        for (int j = 0; j < 4; j++) {
            const float4 kv = kreg[j], vv = vreg[j];
            float hx, hy, hz, hw;
            hx = bflo(kv.x); hy = bflo(kv.y); hz = bflo(kv.z); hw = bflo(kv.w);
            *(uint32_t*)(kh + o + j * 4)     = packbf(hx, hy);
            *(uint32_t*)(kh + o + j * 4 + 2) = packbf(hz, hw);
            *(uint32_t*)(kl + o + j * 4)     = packbf(kv.x - hx, kv.y - hy);
            *(uint32_t*)(kl + o + j * 4 + 2) = packbf(kv.z - hz, kv.w - hw);
            hx = bflo(vv.x); hy = bflo(vv.y); hz = bflo(vv.z); hw = bflo(vv.w);
            *(uint32_t*)(vh + o + j * 4)     = packbf(hx, hy);
            *(uint32_t*)(vh + o + j * 4 + 2) = packbf(hz, hw);
            *(uint32_t*)(vl + o + j * 4)     = packbf(vv.x - hx, vv.y - hy);
            *(uint32_t*)(vl + o + j * 4 + 2) = packbf(vv.z - hz, vv.w - hw);
        }
    };

    /* ---- online softmax state (2 rows/thread) + O accumulators ---- */
    float m_lo = -1e30f, m_hi = -1e30f, l_lo = 0.f, l_hi = 0.f;
    float oacc[8][4];
#pragma unroll
    for (int nf = 0; nf < 8; nf++)
#pragma unroll
        for (int q = 0; q < 4; q++) oacc[nf][q] = 0.f;

    load_regs(0);
    store_tile(0);
    __syncthreads();

    int buf = 0;
    for (int kt = 0; kt < ANKT; kt++) {
        if (kt + 1 < ANKT) load_regs(kt + 1);     /* prefetch to regs */

        /* ---- S = Q K^T (3-product split) ---- */
        float sacc[8][4];
#pragma unroll
        for (int nf = 0; nf < 8; nf++)
#pragma unroll
            for (int q = 0; q < 4; q++) sacc[nf][q] = 0.f;

        const __nv_bfloat16* kh = KH(buf); const __nv_bfloat16* kl = KL(buf);
#pragma unroll
        for (int ks = 0; ks < 4; ks++) {
            uint32_t bh[4][4], bl[4][4];
#pragma unroll
            for (int np = 0; np < 4; np++) {
                const int roff = (np * 16 + ((lane >> 4) << 3) + (lane & 7)) * KP
                               + ks * 16 + (((lane >> 3) & 1) << 3);
                ldmx4(bh[np], kh + roff);
                ldmx4(bl[np], kl + roff);
            }
#pragma unroll
            for (int nf = 0; nf < 8; nf++) {
                const uint32_t b0h = bh[nf >> 1][(nf & 1) * 2];
                const uint32_t b1h = bh[nf >> 1][(nf & 1) * 2 + 1];
                const uint32_t b0l = bl[nf >> 1][(nf & 1) * 2];
                const uint32_t b1l = bl[nf >> 1][(nf & 1) * 2 + 1];
                mma16816(sacc[nf], qfh[ks], b0h, b1h);
                mma16816(sacc[nf], qfh[ks], b0l, b1l);
                mma16816(sacc[nf], qfl[ks], b0h, b1h);
            }
        }

        /* mask invalid keys (only last tile: keys 784.. = nfrags >= 2) */
        if (kt == ANKT - 1) {
#pragma unroll
            for (int nf = 2; nf < 8; nf++)
#pragma unroll
                for (int q = 0; q < 4; q++) sacc[nf][q] = -1e30f;
        }

        /* ---- online softmax ---- */
        float tmlo = -1e30f, tmhi = -1e30f;
#pragma unroll
        for (int nf = 0; nf < 8; nf++) {
            tmlo = fmaxf(tmlo, fmaxf(sacc[nf][0], sacc[nf][1]));
            tmhi = fmaxf(tmhi, fmaxf(sacc[nf][2], sacc[nf][3]));
        }
        tmlo = fmaxf(tmlo, __shfl_xor_sync(0xffffffff, tmlo, 1));
        tmlo = fmaxf(tmlo, __shfl_xor_sync(0xffffffff, tmlo, 2));
        tmhi = fmaxf(tmhi, __shfl_xor_sync(0xffffffff, tmhi, 1));
        tmhi = fmaxf(tmhi, __shfl_xor_sync(0xffffffff, tmhi, 2));

        const float nm_lo = fmaxf(m_lo, tmlo), nm_hi = fmaxf(m_hi, tmhi);
        const float a_lo = __expf(m_lo - nm_lo), a_hi = __expf(m_hi - nm_hi);
        m_lo = nm_lo; m_hi = nm_hi;

        float sum_lo = 0.f, sum_hi = 0.f;
#pragma unroll
        for (int nf = 0; nf < 8; nf++) {
            sacc[nf][0] = __expf(sacc[nf][0] - nm_lo);
            sacc[nf][1] = __expf(sacc[nf][1] - nm_lo);
            sacc[nf][2] = __expf(sacc[nf][2] - nm_hi);
            sacc[nf][3] = __expf(sacc[nf][3] - nm_hi);
            sum_lo += sacc[nf][0] + sacc[nf][1];
            sum_hi += sacc[nf][2] + sacc[nf][3];
        }
        sum_lo += __shfl_xor_sync(0xffffffff, sum_lo, 1);
        sum_lo += __shfl_xor_sync(0xffffffff, sum_lo, 2);
        sum_hi += __shfl_xor_sync(0xffffffff, sum_hi, 1);
        sum_hi += __shfl_xor_sync(0xffffffff, sum_hi, 2);
        l_lo = l_lo * a_lo + sum_lo;
        l_hi = l_hi * a_hi + sum_hi;

#pragma unroll
        for (int nf = 0; nf < 8; nf++) {
            oacc[nf][0] *= a_lo; oacc[nf][1] *= a_lo;
            oacc[nf][2] *= a_hi; oacc[nf][3] *= a_hi;
        }

        /* ---- O += P V (3-product split; P from frags, V via ldmatrix.trans) */
        const __nv_bfloat16* vh = VH(buf); const __nv_bfloat16* vl = VL(buf);
#pragma unroll
        for (int ks = 0; ks < 4; ks++) {
            uint32_t ph[4], pl[4];
            {
                const float* s0 = sacc[2 * ks];
                const float* s1 = sacc[2 * ks + 1];
                float h0 = bflo(s0[0]), h1 = bflo(s0[1]),
                      h2 = bflo(s0[2]), h3 = bflo(s0[3]);
                ph[0] = packbf(h0, h1);  ph[1] = packbf(h2, h3);
                pl[0] = packbf(s0[0] - h0, s0[1] - h1);
                pl[1] = packbf(s0[2] - h2, s0[3] - h3);
                h0 = bflo(s1[0]); h1 = bflo(s1[1]); h2 = bflo(s1[2]); h3 = bflo(s1[3]);
                ph[2] = packbf(h0, h1);  ph[3] = packbf(h2, h3);
                pl[2] = packbf(s1[0] - h0, s1[1] - h1);
                pl[3] = packbf(s1[2] - h2, s1[3] - h3);
            }
            uint32_t wh[4][4], wl[4][4];
#pragma unroll
            for (int np = 0; np < 4; np++) {
                /* trans: bit3 -> key+8, bit4 -> d+8 */
                const int roff = (ks * 16 + (lane & 7) + (((lane >> 3) & 1) << 3)) * KP
                               + np * 16 + (((lane >> 4) & 1) << 3);
                ldmx4t(wh[np], vh + roff);
                ldmx4t(wl[np], vl + roff);
            }
#pragma unroll
            for (int nf = 0; nf < 8; nf++) {
                const uint32_t b0h = wh[nf >> 1][(nf & 1) * 2];
                const uint32_t b1h = wh[nf >> 1][(nf & 1) * 2 + 1];
                const uint32_t b0l = wl[nf >> 1][(nf & 1) * 2];
                const uint32_t b1l = wl[nf >> 1][(nf & 1) * 2 + 1];
                mma16816(oacc[nf], ph, b0h, b1h);
                mma16816(oacc[nf], ph, b0l, b1l);
                mma16816(oacc[nf], pl, b0h, b1h);
            }
        }

        if (kt + 1 < ANKT) store_tile(buf ^ 1);   /* convert + STS next tile */
        __syncthreads();
        buf ^= 1;
    }

    /* ---- normalize + write [b,n,h,d] fp32 ---- */
    const float inv_lo = 1.f / l_lo, inv_hi = 1.f / l_hi;
    const int r_lo = q0 + wid * 16 + (lane >> 2);
    const int r_hi = r_lo + 8;
#pragma unroll
    for (int nf = 0; nf < 8; nf++) {
        const int col = h * HD + nf * 8 + (lane & 3) * 2;
        if (r_lo < SEQ) {
            float2 o = make_float2(oacc[nf][0] * inv_lo, oacc[nf][1] * inv_lo);
            *(float2*)(out + (size_t)(b * SEQ + r_lo) * DIM + col) = o;
        }
        if (r_hi < SEQ) {
            float2 o = make_float2(oacc[nf][2] * inv_hi, oacc[nf][3] * inv_hi);
            *(float2*)(out + (size_t)(b * SEQ + r_hi) * DIM + col) = o;
        }
    }
}

/* ================================ launch =================================== */
extern "C" void kernel_launch(void* const* d_in, const int* in_sizes, int n_in,
                              void* d_out, int out_size)
{
    const float* x    = (const float*)d_in[0];
    const float* Wqkv = (const float*)d_in[1];
    const float* bqkv = (const float*)d_in[2];
    const float* Wo   = (const float*)d_in[3];
    const float* bo   = (const float*)d_in[4];
    float* out = (float*)d_out;

    float *qkv, *att;
    __nv_bfloat16 *xh, *xl, *ath, *atl, *wqh, *wql, *woh, *wol;
    cudaGetSymbolAddress((void**)&qkv, g_qkv);
    cudaGetSymbolAddress((void**)&att, g_att);
    cudaGetSymbolAddress((void**)&xh,  g_xh);
    cudaGetSymbolAddress((void**)&xl,  g_xl);
    cudaGetSymbolAddress((void**)&ath, g_ath);
    cudaGetSymbolAddress((void**)&atl, g_atl);
    cudaGetSymbolAddress((void**)&wqh, g_wqh);
    cudaGetSymbolAddress((void**)&wql, g_wql);
    cudaGetSymbolAddress((void**)&woh, g_woh);
    cudaGetSymbolAddress((void**)&wol, g_wol);

    cudaFuncSetAttribute(attn_mma_kernel, cudaFuncAttributeMaxDynamicSharedMemorySize,
                         ATT_SMEM);

    /* split x into bf16 hi/lo */
    {
        const int n4 = M_TOTAL * DIM / 4;
        split_kernel<<<(n4 + 255) / 256, 256>>>((const float4*)x,
                                                (__nv_bfloat162*)xh,
                                                (__nv_bfloat162*)xl, n4);
    }
    /* transpose+split weights */
    transpose_split_kernel<<<dim3(QKV_N / 32, DIM / 32), 256>>>(Wqkv, wqh, wql, DIM, QKV_N);
    transpose_split_kernel<<<dim3(DIM / 32, DIM / 32), 256>>>(Wo, woh, wol, DIM, DIM);

    /* 1) QKV projection */
    mma_gemm_kernel<<<dim3(QKV_N / 128, M_TOTAL / 128), 256>>>(
        xh, xl, wqh, wql, bqkv, qkv, QKV_N);

    /* 2) tensor-core split flash attention */
    attn_mma_kernel<<<dim3(NQT, NH, BATCH), 256, ATT_SMEM>>>(qkv, att);

    /* 3) split attention output, then output projection */
    {
        const int n4 = M_TOTAL * DIM / 4;
        split_kernel<<<(n4 + 255) / 256, 256>>>((const float4*)att,
                                                (__nv_bfloat162*)ath,
                                                (__nv_bfloat162*)atl, n4);
    }
    mma_gemm_kernel<<<dim3(DIM / 128, M_TOTAL / 128), 256>>>(
        ath, atl, woh, wol, bo, out, DIM);
}

// round 5
// speedup vs baseline: 2.1944x; 1.0404x over previous
#include <cuda_runtime.h>
#include <cuda_bf16.h>
#include <cstdint>

#define DIM    768
#define NH     12
#define HD     64
#define BATCH  16
#define SEQ    784
#define M_TOTAL (BATCH * SEQ)      /* 12544 */
#define QKV_N   (3 * DIM)          /* 2304  */

/* ---------------- scratch (allocation-free rule: __device__ globals) ------- */
__device__ float g_qkv[(size_t)M_TOTAL * QKV_N];   /* [M,3*DIM] fp32 */
__device__ __nv_bfloat16 g_xh[(size_t)M_TOTAL * DIM];
__device__ __nv_bfloat16 g_xl[(size_t)M_TOTAL * DIM];
__device__ __nv_bfloat16 g_ath[(size_t)M_TOTAL * DIM];
__device__ __nv_bfloat16 g_atl[(size_t)M_TOTAL * DIM];
__device__ __nv_bfloat16 g_wqh[(size_t)QKV_N * DIM];   /* W^T [N,K] */
__device__ __nv_bfloat16 g_wql[(size_t)QKV_N * DIM];
__device__ __nv_bfloat16 g_woh[(size_t)DIM * DIM];
__device__ __nv_bfloat16 g_wol[(size_t)DIM * DIM];

/* ========================= PTX helpers (compute_80+) ======================= */
__device__ __forceinline__ uint32_t smem_u32(const void* p) {
    uint32_t a;
    asm("{ .reg .u64 t; cvta.to.shared.u64 t, %1; cvt.u32.u64 %0, t; }"
        : "=r"(a) : "l"(p));
    return a;
}
__device__ __forceinline__ void cp16(uint32_t s, const void* g) {
    asm volatile("cp.async.cg.shared.global [%0], [%1], 16;"
                 :: "r"(s), "l"(g) : "memory");
}
__device__ __forceinline__ void ldmx4(uint32_t* r, const void* p) {
    uint32_t a = smem_u32(p);
    asm volatile("ldmatrix.sync.aligned.m8n8.x4.shared.b16 {%0,%1,%2,%3}, [%4];"
                 : "=r"(r[0]), "=r"(r[1]), "=r"(r[2]), "=r"(r[3]) : "r"(a));
}
__device__ __forceinline__ void ldmx4t(uint32_t* r, const void* p) {
    uint32_t a = smem_u32(p);
    asm volatile("ldmatrix.sync.aligned.m8n8.x4.trans.shared.b16 {%0,%1,%2,%3}, [%4];"
                 : "=r"(r[0]), "=r"(r[1]), "=r"(r[2]), "=r"(r[3]) : "r"(a));
}
__device__ __forceinline__ void mma16816(float* c, const uint32_t* a,
                                         uint32_t b0, uint32_t b1) {
    asm volatile(
        "mma.sync.aligned.m16n8k16.row.col.f32.bf16.bf16.f32 "
        "{%0,%1,%2,%3},{%4,%5,%6,%7},{%8,%9},{%0,%1,%2,%3};"
        : "+f"(c[0]), "+f"(c[1]), "+f"(c[2]), "+f"(c[3])
        : "r"(a[0]), "r"(a[1]), "r"(a[2]), "r"(a[3]), "r"(b0), "r"(b1));
}
__device__ __forceinline__ uint32_t packbf(float x, float y) {
    __nv_bfloat162 t = __halves2bfloat162(__float2bfloat16(x), __float2bfloat16(y));
    return *reinterpret_cast<uint32_t*>(&t);
}
__device__ __forceinline__ float bflo(float x) {
    return __bfloat162float(__float2bfloat16(x));
}

/* ======================= split / transpose kernels ========================= */
__global__ __launch_bounds__(256)
void split_kernel(const float4* __restrict__ in, __nv_bfloat162* __restrict__ hi,
                  __nv_bfloat162* __restrict__ lo, int n4)
{
    int i = blockIdx.x * 256 + threadIdx.x;
    if (i >= n4) return;
    float4 v = in[i];
    __nv_bfloat16 hx = __float2bfloat16(v.x), hy = __float2bfloat16(v.y);
    __nv_bfloat16 hz = __float2bfloat16(v.z), hw = __float2bfloat16(v.w);
    hi[2 * i + 0] = __halves2bfloat162(hx, hy);
    hi[2 * i + 1] = __halves2bfloat162(hz, hw);
    lo[2 * i + 0] = __halves2bfloat162(__float2bfloat16(v.x - __bfloat162float(hx)),
                                       __float2bfloat16(v.y - __bfloat162float(hy)));
    lo[2 * i + 1] = __halves2bfloat162(__float2bfloat16(v.z - __bfloat162float(hz)),
                                       __float2bfloat16(v.w - __bfloat162float(hw)));
}

/* in [K,N] fp32 -> hi/lo [N,K] bf16 */
__global__ __launch_bounds__(256)
void transpose_split_kernel(const float* __restrict__ in, __nv_bfloat16* __restrict__ hi,
                            __nv_bfloat16* __restrict__ lo, int K, int N)
{
    __shared__ float t[32][33];
    const int k0 = blockIdx.y * 32, n0 = blockIdx.x * 32;
    const int tx = threadIdx.x & 31, ty = threadIdx.x >> 5;
#pragma unroll
    for (int i = 0; i < 32; i += 8)
        t[ty + i][tx] = in[(size_t)(k0 + ty + i) * N + n0 + tx];
    __syncthreads();
#pragma unroll
    for (int i = 0; i < 32; i += 8) {
        const int n = n0 + ty + i, k = k0 + tx;
        const float v = t[tx][ty + i];
        const __nv_bfloat16 h = __float2bfloat16(v);
        hi[(size_t)n * K + k] = h;
        lo[(size_t)n * K + k] = __float2bfloat16(v - __bfloat162float(h));
    }
}

/* ============== mma.sync bf16 split-GEMM, 4-stage cp.async ================ */
#define BKH    32
#define NCHP   (DIM / BKH)            /* 24 */
#define NITER  (3 * NCHP)             /* 72 */
#define PITCH  40                     /* halves; 80B rows, xbar-clean          */
#define STAGES 4
#define STG_HALVES (128 * PITCH)      /* per array per stage                   */
#define GEMM_SMEM (STAGES * 2 * STG_HALVES * 2)   /* 81920 B */

__global__ __launch_bounds__(256)
void mma_gemm_kernel(const __nv_bfloat16* __restrict__ Ah, const __nv_bfloat16* __restrict__ Al,
                     const __nv_bfloat16* __restrict__ Bh, const __nv_bfloat16* __restrict__ Bl,
                     const float* __restrict__ bias, float* __restrict__ C, int Ntot)
{
    extern __shared__ __nv_bfloat16 gs[];

    const int tid = threadIdx.x;
    const int wid = tid >> 5, lane = tid & 31;
    const int wm = wid & 3, wn = wid >> 2;
    const int bx = blockIdx.x, by = blockIdx.y;

    const __nv_bfloat16* Asel[3] = { Ah, Ah, Al };
    const __nv_bfloat16* Bsel[3] = { Bh, Bl, Bh };

    const int r0c = (tid * 2) >> 2, c0c = (tid * 2) & 3;
    const int r1c = (tid * 2 + 1) >> 2, c1c = (tid * 2 + 1) & 3;

    auto As = [&](int s) { return gs + (size_t)s * 2 * STG_HALVES; };
    auto Bs = [&](int s) { return As(s) + STG_HALVES; };

    auto load_tile = [&](int it, int s) {
        const int p = it / NCHP, kc = it % NCHP;
        const __nv_bfloat16* Ap = Asel[p] + (size_t)(by * 128) * DIM + kc * BKH;
        const __nv_bfloat16* Bp = Bsel[p] + (size_t)(bx * 128) * DIM + kc * BKH;
        uint32_t sa = smem_u32(As(s));
        uint32_t sb = smem_u32(Bs(s));
        cp16(sa + (r0c * PITCH + c0c * 8) * 2, Ap + (size_t)r0c * DIM + c0c * 8);
        cp16(sa + (r1c * PITCH + c1c * 8) * 2, Ap + (size_t)r1c * DIM + c1c * 8);
        cp16(sb + (r0c * PITCH + c0c * 8) * 2, Bp + (size_t)r0c * DIM + c0c * 8);
        cp16(sb + (r1c * PITCH + c1c * 8) * 2, Bp + (size_t)r1c * DIM + c1c * 8);
        asm volatile("cp.async.commit_group;" ::: "memory");
    };

    float acc[2][8][4];
#pragma unroll
    for (int mf = 0; mf < 2; mf++)
#pragma unroll
        for (int nf = 0; nf < 8; nf++)
#pragma unroll
            for (int q = 0; q < 4; q++) acc[mf][nf][q] = 0.f;

    /* prologue: fill 3 stages */
    load_tile(0, 0);
    load_tile(1, 1);
    load_tile(2, 2);

#pragma unroll 1
    for (int it = 0; it < NITER; it++) {
        const int rem = NITER - 1 - it;
        if (rem >= 2)      asm volatile("cp.async.wait_group 2;" ::: "memory");
        else if (rem == 1) asm volatile("cp.async.wait_group 1;" ::: "memory");
        else               asm volatile("cp.async.wait_group 0;" ::: "memory");
        __syncthreads();

        if (it + 3 < NITER) load_tile(it + 3, (it + 3) & (STAGES - 1));

        const __nv_bfloat16* Ab = As(it & (STAGES - 1));
        const __nv_bfloat16* Bb = Bs(it & (STAGES - 1));
#pragma unroll
        for (int ks = 0; ks < 2; ks++) {
            uint32_t ar[2][4];
#pragma unroll
            for (int mf = 0; mf < 2; mf++)
                ldmx4(ar[mf],
                      Ab + (wm * 32 + mf * 16 + (lane & 15)) * PITCH
                         + ks * 16 + (lane >> 4) * 8);
            uint32_t br[4][4];
#pragma unroll
            for (int np = 0; np < 4; np++)
                ldmx4(br[np],
                      Bb + (wn * 64 + np * 16 + ((lane >> 4) << 3) + (lane & 7)) * PITCH
                         + ks * 16 + (((lane >> 3) & 1) << 3));
#pragma unroll
            for (int mf = 0; mf < 2; mf++)
#pragma unroll
                for (int nf = 0; nf < 8; nf++)
                    mma16816(acc[mf][nf], ar[mf],
                             br[nf >> 1][(nf & 1) * 2],
                             br[nf >> 1][(nf & 1) * 2 + 1]);
        }
    }

    const int rbase = by * 128 + wm * 32;
    const int cbase = bx * 128 + wn * 64;
#pragma unroll
    for (int mf = 0; mf < 2; mf++) {
        const int row = rbase + mf * 16 + (lane >> 2);
#pragma unroll
        for (int nf = 0; nf < 8; nf++) {
            const int col = cbase + nf * 8 + (lane & 3) * 2;
            const float2 bv = *(const float2*)(bias + col);
            float2 o0, o1;
            o0.x = acc[mf][nf][0] + bv.x;  o0.y = acc[mf][nf][1] + bv.y;
            o1.x = acc[mf][nf][2] + bv.x;  o1.y = acc[mf][nf][3] + bv.y;
            *(float2*)(C + (size_t)row * Ntot + col) = o0;
            *(float2*)(C + (size_t)(row + 8) * Ntot + col) = o1;
        }
    }
}

/* ====================== mma.sync split flash attention ===================== */
#define ATQ  128
#define ATK  64
#define NQT  7
#define ANKT 13
#define KP   72
#define TILE_HALVES (ATK * KP)
#define ATT_SMEM (2 * 4 * TILE_HALVES * 2)

__global__ __launch_bounds__(256)
void attn_mma_kernel(const float* __restrict__ qkv,
                     __nv_bfloat16* __restrict__ oh, __nv_bfloat16* __restrict__ ol)
{
    extern __shared__ __nv_bfloat16 sh[];
    const int tid = threadIdx.x, wid = tid >> 5, lane = tid & 31;
    const int qt = blockIdx.x, h = blockIdx.y, b = blockIdx.z;
    const int q0 = qt * ATQ;

    auto KH = [&](int buf) { return sh + (size_t)buf * 4 * TILE_HALVES; };
    auto KL = [&](int buf) { return KH(buf) + TILE_HALVES; };
    auto VH = [&](int buf) { return KH(buf) + 2 * TILE_HALVES; };
    auto VL = [&](int buf) { return KH(buf) + 3 * TILE_HALVES; };

    uint32_t qfh[4][4], qfl[4][4];
#pragma unroll
    for (int kb = 0; kb < 4; kb++)
#pragma unroll
        for (int i = 0; i < 4; i++) {
            const int row = ((i & 1) << 3) + (lane >> 2);
            const int kofs = kb * 16 + ((i >> 1) << 3) + ((lane & 3) << 1);
            int qg = q0 + wid * 16 + row;
            if (qg > SEQ - 1) qg = SEQ - 1;
            const float2 qv = *(const float2*)(qkv + (size_t)(b * SEQ + qg) * QKV_N
                                               + h * HD + kofs);
            const float sx = qv.x * 0.125f, sy = qv.y * 0.125f;
            const float hx = bflo(sx), hy = bflo(sy);
            qfh[kb][i] = packbf(hx, hy);
            qfl[kb][i] = packbf(sx - hx, sy - hy);
        }

    const int lkey = tid >> 2, ldb = tid & 3;
    float4 kreg[4], vreg[4];

    auto load_regs = [&](int kt) {
        int kg = kt * ATK + lkey;
        if (kg > SEQ - 1) kg = SEQ - 1;
        const float* base = qkv + (size_t)(b * SEQ + kg) * QKV_N + h * HD + ldb * 16;
#pragma unroll
        for (int j = 0; j < 4; j++) {
            kreg[j] = *(const float4*)(base + DIM + j * 4);
            vreg[j] = *(const float4*)(base + 2 * DIM + j * 4);
        }
    };
    auto store_tile = [&](int buf) {
        __nv_bfloat16* kh = KH(buf); __nv_bfloat16* kl = KL(buf);
        __nv_bfloat16* vh = VH(buf); __nv_bfloat16* vl = VL(buf);
        const int o = lkey * KP + ldb * 16;
#pragma unroll
        for (int j = 0; j < 4; j++) {
            const float4 kv = kreg[j], vv = vreg[j];
            float hx, hy, hz, hw;
            hx = bflo(kv.x); hy = bflo(kv.y); hz = bflo(kv.z); hw = bflo(kv.w);
            *(uint32_t*)(kh + o + j * 4)     = packbf(hx, hy);
            *(uint32_t*)(kh + o + j * 4 + 2) = packbf(hz, hw);
            *(uint32_t*)(kl + o + j * 4)     = packbf(kv.x - hx, kv.y - hy);
            *(uint32_t*)(kl + o + j * 4 + 2) = packbf(kv.z - hz, kv.w - hw);
            hx = bflo(vv.x); hy = bflo(vv.y); hz = bflo(vv.z); hw = bflo(vv.w);
            *(uint32_t*)(vh + o + j * 4)     = packbf(hx, hy);
            *(uint32_t*)(vh + o + j * 4 + 2) = packbf(hz, hw);
            *(uint32_t*)(vl + o + j * 4)     = packbf(vv.x - hx, vv.y - hy);
            *(uint32_t*)(vl + o + j * 4 + 2) = packbf(vv.z - hz, vv.w - hw);
        }
    };

    float m_lo = -1e30f, m_hi = -1e30f, l_lo = 0.f, l_hi = 0.f;
    float oacc[8][4];
#pragma unroll
    for (int nf = 0; nf < 8; nf++)
#pragma unroll
        for (int q = 0; q < 4; q++) oacc[nf][q] = 0.f;

    load_regs(0);
    store_tile(0);
    __syncthreads();

    int buf = 0;
    for (int kt = 0; kt < ANKT; kt++) {
        if (kt + 1 < ANKT) load_regs(kt + 1);

        float sacc[8][4];
#pragma unroll
        for (int nf = 0; nf < 8; nf++)
#pragma unroll
            for (int q = 0; q < 4; q++) sacc[nf][q] = 0.f;

        const __nv_bfloat16* kh = KH(buf); const __nv_bfloat16* kl = KL(buf);
#pragma unroll
        for (int ks = 0; ks < 4; ks++) {
            uint32_t bh[4][4], bl[4][4];
#pragma unroll
            for (int np = 0; np < 4; np++) {
                const int roff = (np * 16 + ((lane >> 4) << 3) + (lane & 7)) * KP
                               + ks * 16 + (((lane >> 3) & 1) << 3);
                ldmx4(bh[np], kh + roff);
                ldmx4(bl[np], kl + roff);
            }
#pragma unroll
            for (int nf = 0; nf < 8; nf++) {
                const uint32_t b0h = bh[nf >> 1][(nf & 1) * 2];
                const uint32_t b1h = bh[nf >> 1][(nf & 1) * 2 + 1];
                const uint32_t b0l = bl[nf >> 1][(nf & 1) * 2];
                const uint32_t b1l = bl[nf >> 1][(nf & 1) * 2 + 1];
                mma16816(sacc[nf], qfh[ks], b0h, b1h);
                mma16816(sacc[nf], qfh[ks], b0l, b1l);
                mma16816(sacc[nf], qfl[ks], b0h, b1h);
            }
        }

        if (kt == ANKT - 1) {
#pragma unroll
            for (int nf = 2; nf < 8; nf++)
#pragma unroll
                for (int q = 0; q < 4; q++) sacc[nf][q] = -1e30f;
        }

        float tmlo = -1e30f, tmhi = -1e30f;
#pragma unroll
        for (int nf = 0; nf < 8; nf++) {
            tmlo = fmaxf(tmlo, fmaxf(sacc[nf][0], sacc[nf][1]));
            tmhi = fmaxf(tmhi, fmaxf(sacc[nf][2], sacc[nf][3]));
        }
        tmlo = fmaxf(tmlo, __shfl_xor_sync(0xffffffff, tmlo, 1));
        tmlo = fmaxf(tmlo, __shfl_xor_sync(0xffffffff, tmlo, 2));
        tmhi = fmaxf(tmhi, __shfl_xor_sync(0xffffffff, tmhi, 1));
        tmhi = fmaxf(tmhi, __shfl_xor_sync(0xffffffff, tmhi, 2));

        const float nm_lo = fmaxf(m_lo, tmlo), nm_hi = fmaxf(m_hi, tmhi);
        const float a_lo = __expf(m_lo - nm_lo), a_hi = __expf(m_hi - nm_hi);
        m_lo = nm_lo; m_hi = nm_hi;

        float sum_lo = 0.f, sum_hi = 0.f;
#pragma unroll
        for (int nf = 0; nf < 8; nf++) {
            sacc[nf][0] = __expf(sacc[nf][0] - nm_lo);
            sacc[nf][1] = __expf(sacc[nf][1] - nm_lo);
            sacc[nf][2] = __expf(sacc[nf][2] - nm_hi);
            sacc[nf][3] = __expf(sacc[nf][3] - nm_hi);
            sum_lo += sacc[nf][0] + sacc[nf][1];
            sum_hi += sacc[nf][2] + sacc[nf][3];
        }
        sum_lo += __shfl_xor_sync(0xffffffff, sum_lo, 1);
        sum_lo += __shfl_xor_sync(0xffffffff, sum_lo, 2);
        sum_hi += __shfl_xor_sync(0xffffffff, sum_hi, 1);
        sum_hi += __shfl_xor_sync(0xffffffff, sum_hi, 2);
        l_lo = l_lo * a_lo + sum_lo;
        l_hi = l_hi * a_hi + sum_hi;

#pragma unroll
        for (int nf = 0; nf < 8; nf++) {
            oacc[nf][0] *= a_lo; oacc[nf][1] *= a_lo;
            oacc[nf][2] *= a_hi; oacc[nf][3] *= a_hi;
        }

        const __nv_bfloat16* vh = VH(buf); const __nv_bfloat16* vl = VL(buf);
#pragma unroll
        for (int ks = 0; ks < 4; ks++) {
            uint32_t ph[4], pl[4];
            {
                const float* s0 = sacc[2 * ks];
                const float* s1 = sacc[2 * ks + 1];
                float h0 = bflo(s0[0]), h1 = bflo(s0[1]),
                      h2 = bflo(s0[2]), h3 = bflo(s0[3]);
                ph[0] = packbf(h0, h1);  ph[1] = packbf(h2, h3);
                pl[0] = packbf(s0[0] - h0, s0[1] - h1);
                pl[1] = packbf(s0[2] - h2, s0[3] - h3);
                h0 = bflo(s1[0]); h1 = bflo(s1[1]); h2 = bflo(s1[2]); h3 = bflo(s1[3]);
                ph[2] = packbf(h0, h1);  ph[3] = packbf(h2, h3);
                pl[2] = packbf(s1[0] - h0, s1[1] - h1);
                pl[3] = packbf(s1[2] - h2, s1[3] - h3);
            }
            uint32_t wh[4][4], wl[4][4];
#pragma unroll
            for (int np = 0; np < 4; np++) {
                const int roff = (ks * 16 + (lane & 7) + (((lane >> 3) & 1) << 3)) * KP
                               + np * 16 + (((lane >> 4) & 1) << 3);
                ldmx4t(wh[np], vh + roff);
                ldmx4t(wl[np], vl + roff);
            }
#pragma unroll
            for (int nf = 0; nf < 8; nf++) {
                const uint32_t b0h = wh[nf >> 1][(nf & 1) * 2];
                const uint32_t b1h = wh[nf >> 1][(nf & 1) * 2 + 1];
                const uint32_t b0l = wl[nf >> 1][(nf & 1) * 2];
                const uint32_t b1l = wl[nf >> 1][(nf & 1) * 2 + 1];
                mma16816(oacc[nf], ph, b0h, b1h);
                mma16816(oacc[nf], ph, b0l, b1l);
                mma16816(oacc[nf], pl, b0h, b1h);
            }
        }

        if (kt + 1 < ANKT) store_tile(buf ^ 1);
        __syncthreads();
        buf ^= 1;
    }

    /* normalize + write bf16 hi/lo directly (feeds out-proj split-GEMM) */
    const float inv_lo = 1.f / l_lo, inv_hi = 1.f / l_hi;
    const int r_lo = q0 + wid * 16 + (lane >> 2);
    const int r_hi = r_lo + 8;
#pragma unroll
    for (int nf = 0; nf < 8; nf++) {
        const int col = h * HD + nf * 8 + (lane & 3) * 2;
        if (r_lo < SEQ) {
            const float v0 = oacc[nf][0] * inv_lo, v1 = oacc[nf][1] * inv_lo;
            const float hx = bflo(v0), hy = bflo(v1);
            *(uint32_t*)(oh + (size_t)(b * SEQ + r_lo) * DIM + col) = packbf(hx, hy);
            *(uint32_t*)(ol + (size_t)(b * SEQ + r_lo) * DIM + col) =
                packbf(v0 - hx, v1 - hy);
        }
        if (r_hi < SEQ) {
            const float v0 = oacc[nf][2] * inv_hi, v1 = oacc[nf][3] * inv_hi;
            const float hx = bflo(v0), hy = bflo(v1);
            *(uint32_t*)(oh + (size_t)(b * SEQ + r_hi) * DIM + col) = packbf(hx, hy);
            *(uint32_t*)(ol + (size_t)(b * SEQ + r_hi) * DIM + col) =
                packbf(v0 - hx, v1 - hy);
        }
    }
}

/* ================================ launch =================================== */
extern "C" void kernel_launch(void* const* d_in, const int* in_sizes, int n_in,
                              void* d_out, int out_size)
{
    const float* x    = (const float*)d_in[0];
    const float* Wqkv = (const float*)d_in[1];
    const float* bqkv = (const float*)d_in[2];
    const float* Wo   = (const float*)d_in[3];
    const float* bo   = (const float*)d_in[4];
    float* out = (float*)d_out;

    float *qkv;
    __nv_bfloat16 *xh, *xl, *ath, *atl, *wqh, *wql, *woh, *wol;
    cudaGetSymbolAddress((void**)&qkv, g_qkv);
    cudaGetSymbolAddress((void**)&xh,  g_xh);
    cudaGetSymbolAddress((void**)&xl,  g_xl);
    cudaGetSymbolAddress((void**)&ath, g_ath);
    cudaGetSymbolAddress((void**)&atl, g_atl);
    cudaGetSymbolAddress((void**)&wqh, g_wqh);
    cudaGetSymbolAddress((void**)&wql, g_wql);
    cudaGetSymbolAddress((void**)&woh, g_woh);
    cudaGetSymbolAddress((void**)&wol, g_wol);

    cudaFuncSetAttribute(mma_gemm_kernel, cudaFuncAttributeMaxDynamicSharedMemorySize,
                         GEMM_SMEM);
    cudaFuncSetAttribute(attn_mma_kernel, cudaFuncAttributeMaxDynamicSharedMemorySize,
                         ATT_SMEM);

    /* split x into bf16 hi/lo */
    {
        const int n4 = M_TOTAL * DIM / 4;
        split_kernel<<<(n4 + 255) / 256, 256>>>((const float4*)x,
                                                (__nv_bfloat162*)xh,
                                                (__nv_bfloat162*)xl, n4);
    }
    /* transpose+split weights */
    transpose_split_kernel<<<dim3(QKV_N / 32, DIM / 32), 256>>>(Wqkv, wqh, wql, DIM, QKV_N);
    transpose_split_kernel<<<dim3(DIM / 32, DIM / 32), 256>>>(Wo, woh, wol, DIM, DIM);

    /* 1) QKV projection */
    mma_gemm_kernel<<<dim3(QKV_N / 128, M_TOTAL / 128), 256, GEMM_SMEM>>>(
        xh, xl, wqh, wql, bqkv, qkv, QKV_N);

    /* 2) tensor-core split flash attention (writes bf16 hi/lo directly) */
    attn_mma_kernel<<<dim3(NQT, NH, BATCH), 256, ATT_SMEM>>>(qkv, ath, atl);

    /* 3) output projection */
    mma_gemm_kernel<<<dim3(DIM / 128, M_TOTAL / 128), 256, GEMM_SMEM>>>(
        ath, atl, woh, wol, bo, out, DIM);
}

// round 6
// speedup vs baseline: 2.6762x; 1.2195x over previous
#include <cuda_runtime.h>
#include <cuda_bf16.h>
#include <cstdint>

#define DIM    768
#define NH     12
#define HD     64
#define BATCH  16
#define SEQ    784
#define M_TOTAL (BATCH * SEQ)      /* 12544 */
#define QKV_N   (3 * DIM)          /* 2304  */
#define KVSZ   ((size_t)BATCH * NH * SEQ * HD)

/* ---------------- scratch (allocation-free rule: __device__ globals) ------- */
__device__ float g_q[(size_t)M_TOTAL * DIM];          /* Q fp32 [b,n,h,d]      */
__device__ __nv_bfloat16 g_kh[KVSZ + 8192];           /* K/V split [b,h,n,d]   */
__device__ __nv_bfloat16 g_kl[KVSZ + 8192];
__device__ __nv_bfloat16 g_vh[KVSZ + 8192];
__device__ __nv_bfloat16 g_vl[KVSZ + 8192];
__device__ __nv_bfloat16 g_xh[(size_t)M_TOTAL * DIM];
__device__ __nv_bfloat16 g_xl[(size_t)M_TOTAL * DIM];
__device__ __nv_bfloat16 g_ath[(size_t)M_TOTAL * DIM];
__device__ __nv_bfloat16 g_atl[(size_t)M_TOTAL * DIM];
__device__ __nv_bfloat16 g_wqh[(size_t)QKV_N * DIM];  /* W^T [N,K] */
__device__ __nv_bfloat16 g_wql[(size_t)QKV_N * DIM];
__device__ __nv_bfloat16 g_woh[(size_t)DIM * DIM];
__device__ __nv_bfloat16 g_wol[(size_t)DIM * DIM];

/* ========================= PTX helpers (compute_80+) ======================= */
__device__ __forceinline__ uint32_t smem_u32(const void* p) {
    uint32_t a;
    asm("{ .reg .u64 t; cvta.to.shared.u64 t, %1; cvt.u32.u64 %0, t; }"
        : "=r"(a) : "l"(p));
    return a;
}
__device__ __forceinline__ void cp16(uint32_t s, const void* g) {
    asm volatile("cp.async.cg.shared.global [%0], [%1], 16;"
                 :: "r"(s), "l"(g) : "memory");
}
__device__ __forceinline__ void ldmx4(uint32_t* r, const void* p) {
    uint32_t a = smem_u32(p);
    asm volatile("ldmatrix.sync.aligned.m8n8.x4.shared.b16 {%0,%1,%2,%3}, [%4];"
                 : "=r"(r[0]), "=r"(r[1]), "=r"(r[2]), "=r"(r[3]) : "r"(a));
}
__device__ __forceinline__ void ldmx4t(uint32_t* r, const void* p) {
    uint32_t a = smem_u32(p);
    asm volatile("ldmatrix.sync.aligned.m8n8.x4.trans.shared.b16 {%0,%1,%2,%3}, [%4];"
                 : "=r"(r[0]), "=r"(r[1]), "=r"(r[2]), "=r"(r[3]) : "r"(a));
}
__device__ __forceinline__ void mma16816(float* c, const uint32_t* a,
                                         uint32_t b0, uint32_t b1) {
    asm volatile(
        "mma.sync.aligned.m16n8k16.row.col.f32.bf16.bf16.f32 "
        "{%0,%1,%2,%3},{%4,%5,%6,%7},{%8,%9},{%0,%1,%2,%3};"
        : "+f"(c[0]), "+f"(c[1]), "+f"(c[2]), "+f"(c[3])
        : "r"(a[0]), "r"(a[1]), "r"(a[2]), "r"(a[3]), "r"(b0), "r"(b1));
}
__device__ __forceinline__ uint32_t packbf(float x, float y) {
    __nv_bfloat162 t = __halves2bfloat162(__float2bfloat16(x), __float2bfloat16(y));
    return *reinterpret_cast<uint32_t*>(&t);
}
__device__ __forceinline__ float bflo(float x) {
    return __bfloat162float(__float2bfloat16(x));
}

/* ======================= split / transpose kernels ========================= */
__global__ __launch_bounds__(256)
void split_kernel(const float4* __restrict__ in, __nv_bfloat162* __restrict__ hi,
                  __nv_bfloat162* __restrict__ lo, int n4)
{
    int i = blockIdx.x * 256 + threadIdx.x;
    if (i >= n4) return;
    float4 v = in[i];
    __nv_bfloat16 hx = __float2bfloat16(v.x), hy = __float2bfloat16(v.y);
    __nv_bfloat16 hz = __float2bfloat16(v.z), hw = __float2bfloat16(v.w);
    hi[2 * i + 0] = __halves2bfloat162(hx, hy);
    hi[2 * i + 1] = __halves2bfloat162(hz, hw);
    lo[2 * i + 0] = __halves2bfloat162(__float2bfloat16(v.x - __bfloat162float(hx)),
                                       __float2bfloat16(v.y - __bfloat162float(hy)));
    lo[2 * i + 1] = __halves2bfloat162(__float2bfloat16(v.z - __bfloat162float(hz)),
                                       __float2bfloat16(v.w - __bfloat162float(hw)));
}

__global__ __launch_bounds__(256)
void transpose_split_kernel(const float* __restrict__ in, __nv_bfloat16* __restrict__ hi,
                            __nv_bfloat16* __restrict__ lo, int K, int N)
{
    __shared__ float t[32][33];
    const int k0 = blockIdx.y * 32, n0 = blockIdx.x * 32;
    const int tx = threadIdx.x & 31, ty = threadIdx.x >> 5;
#pragma unroll
    for (int i = 0; i < 32; i += 8)
        t[ty + i][tx] = in[(size_t)(k0 + ty + i) * N + n0 + tx];
    __syncthreads();
#pragma unroll
    for (int i = 0; i < 32; i += 8) {
        const int n = n0 + ty + i, k = k0 + tx;
        const float v = t[tx][ty + i];
        const __nv_bfloat16 h = __float2bfloat16(v);
        hi[(size_t)n * K + k] = h;
        lo[(size_t)n * K + k] = __float2bfloat16(v - __bfloat162float(h));
    }
}

/* ============ mma.sync bf16 split-GEMM, BK=64, 3-stage cp.async ============ */
#define BKH    64
#define NCHP   (DIM / BKH)            /* 12 */
#define NITER  (3 * NCHP)             /* 36 */
#define PITCH  72                     /* halves: 144B rows, xbar-clean         */
#define STAGES 3
#define STG_HALVES (128 * PITCH)      /* 9216 halves per array per stage       */
#define GEMM_SMEM (STAGES * 2 * STG_HALVES * 2)   /* 110592 B */

/* mode 0: C fp32 + bias.  mode 1: QKV scatter (q fp32; K/V split bf16). */
__global__ __launch_bounds__(256)
void mma_gemm_kernel(const __nv_bfloat16* __restrict__ Ah, const __nv_bfloat16* __restrict__ Al,
                     const __nv_bfloat16* __restrict__ Bh, const __nv_bfloat16* __restrict__ Bl,
                     const float* __restrict__ bias, float* __restrict__ C, int Ntot,
                     int mode,
                     __nv_bfloat16* __restrict__ kh_g, __nv_bfloat16* __restrict__ kl_g,
                     __nv_bfloat16* __restrict__ vh_g, __nv_bfloat16* __restrict__ vl_g)
{
    extern __shared__ __nv_bfloat16 gs[];

    const int tid = threadIdx.x;
    const int wid = tid >> 5, lane = tid & 31;
    const int wm = wid & 3, wn = wid >> 2;
    const int bx = blockIdx.x, by = blockIdx.y;

    const __nv_bfloat16* Asel[3] = { Ah, Ah, Al };
    const __nv_bfloat16* Bsel[3] = { Bh, Bl, Bh };

    const int lrow = tid >> 3, lc = tid & 7;   /* 4 rows per thread via +32 */

    auto As = [&](int s) { return gs + (size_t)s * 2 * STG_HALVES; };
    auto Bs = [&](int s) { return As(s) + STG_HALVES; };

    auto load_tile = [&](int it, int s) {
        const int p = it / NCHP, kc = it - p * NCHP;
        const __nv_bfloat16* Ap = Asel[p] + (size_t)(by * 128) * DIM + kc * BKH;
        const __nv_bfloat16* Bp = Bsel[p] + (size_t)(bx * 128) * DIM + kc * BKH;
        uint32_t sa = smem_u32(As(s));
        uint32_t sb = smem_u32(Bs(s));
#pragma unroll
        for (int t = 0; t < 4; t++) {
            const int row = lrow + t * 32;
            cp16(sa + (row * PITCH + lc * 8) * 2, Ap + (size_t)row * DIM + lc * 8);
            cp16(sb + (row * PITCH + lc * 8) * 2, Bp + (size_t)row * DIM + lc * 8);
        }
        asm volatile("cp.async.commit_group;" ::: "memory");
    };

    float acc[2][8][4];
#pragma unroll
    for (int mf = 0; mf < 2; mf++)
#pragma unroll
        for (int nf = 0; nf < 8; nf++)
#pragma unroll
            for (int q = 0; q < 4; q++) acc[mf][nf][q] = 0.f;

    load_tile(0, 0);
    load_tile(1, 1);

    int cs = 0, ps = 2;
#pragma unroll 1
    for (int it = 0; it < NITER; it++) {
        if (it == NITER - 1) asm volatile("cp.async.wait_group 0;" ::: "memory");
        else                 asm volatile("cp.async.wait_group 1;" ::: "memory");
        __syncthreads();

        if (it + 2 < NITER) {
            load_tile(it + 2, ps);
            ps = (ps + 1 == STAGES) ? 0 : ps + 1;
        }

        const __nv_bfloat16* Ab = As(cs);
        const __nv_bfloat16* Bb = Bs(cs);
        cs = (cs + 1 == STAGES) ? 0 : cs + 1;

#pragma unroll
        for (int ks = 0; ks < 4; ks++) {
            uint32_t ar[2][4];
#pragma unroll
            for (int mf = 0; mf < 2; mf++)
                ldmx4(ar[mf],
                      Ab + (wm * 32 + mf * 16 + (lane & 15)) * PITCH
                         + ks * 16 + (lane >> 4) * 8);
            uint32_t br[4][4];
#pragma unroll
            for (int np = 0; np < 4; np++)
                ldmx4(br[np],
                      Bb + (wn * 64 + np * 16 + ((lane >> 4) << 3) + (lane & 7)) * PITCH
                         + ks * 16 + (((lane >> 3) & 1) << 3));
#pragma unroll
            for (int mf = 0; mf < 2; mf++)
#pragma unroll
                for (int nf = 0; nf < 8; nf++)
                    mma16816(acc[mf][nf], ar[mf],
                             br[nf >> 1][(nf & 1) * 2],
                             br[nf >> 1][(nf & 1) * 2 + 1]);
        }
    }

    const int rbase = by * 128 + wm * 32;
    const int cbase = bx * 128 + wn * 64;

    if (mode == 0) {
#pragma unroll
        for (int mf = 0; mf < 2; mf++) {
            const int row = rbase + mf * 16 + (lane >> 2);
#pragma unroll
            for (int nf = 0; nf < 8; nf++) {
                const int col = cbase + nf * 8 + (lane & 3) * 2;
                const float2 bv = *(const float2*)(bias + col);
                float2 o0, o1;
                o0.x = acc[mf][nf][0] + bv.x;  o0.y = acc[mf][nf][1] + bv.y;
                o1.x = acc[mf][nf][2] + bv.x;  o1.y = acc[mf][nf][3] + bv.y;
                *(float2*)(C + (size_t)row * Ntot + col) = o0;
                *(float2*)(C + (size_t)(row + 8) * Ntot + col) = o1;
            }
        }
    } else {
#pragma unroll
        for (int mf = 0; mf < 2; mf++) {
#pragma unroll
            for (int nf = 0; nf < 8; nf++) {
                const int col = cbase + nf * 8 + (lane & 3) * 2;
                const float2 bv = *(const float2*)(bias + col);
#pragma unroll
                for (int half = 0; half < 2; half++) {
                    const int row = rbase + mf * 16 + (lane >> 2) + half * 8;
                    const float v0 = acc[mf][nf][half * 2 + 0] + bv.x;
                    const float v1 = acc[mf][nf][half * 2 + 1] + bv.y;
                    const int b = row / SEQ, n = row - b * SEQ;
                    if (col < DIM) {
                        float2 o; o.x = v0; o.y = v1;
                        *(float2*)(C + (size_t)row * DIM + col) = o;
                    } else {
                        const int sec = (col < 2 * DIM) ? 0 : 1;
                        const int local = col - DIM - sec * DIM;
                        const int h = local >> 6, d = local & 63;
                        const size_t idx = ((size_t)(b * NH + h) * SEQ + n) * HD + d;
                        const float h0 = bflo(v0), h1 = bflo(v1);
                        __nv_bfloat16* dh = sec ? vh_g : kh_g;
                        __nv_bfloat16* dl = sec ? vl_g : kl_g;
                        *(uint32_t*)(dh + idx) = packbf(h0, h1);
                        *(uint32_t*)(dl + idx) = packbf(v0 - h0, v1 - h1);
                    }
                }
            }
        }
    }
}

/* ====================== mma.sync split flash attention ===================== */
#define ATQ  128
#define ATK  64
#define NQT  7
#define ANKT 13
#define KP   72
#define TILE_HALVES (ATK * KP)
#define ATT_SMEM (2 * 4 * TILE_HALVES * 2)

__global__ __launch_bounds__(256)
void attn_mma_kernel(const float* __restrict__ qsrc,
                     const __nv_bfloat16* __restrict__ kh_g,
                     const __nv_bfloat16* __restrict__ kl_g,
                     const __nv_bfloat16* __restrict__ vh_g,
                     const __nv_bfloat16* __restrict__ vl_g,
                     __nv_bfloat16* __restrict__ oh, __nv_bfloat16* __restrict__ ol)
{
    extern __shared__ __nv_bfloat16 sh[];
    const int tid = threadIdx.x, wid = tid >> 5, lane = tid & 31;
    const int qt = blockIdx.x, h = blockIdx.y, b = blockIdx.z;
    const int q0 = qt * ATQ;

    auto BUF = [&](int buf) { return sh + (size_t)buf * 4 * TILE_HALVES; };

    /* ---- Q fragments (persistent, pre-scaled, hi/lo split) ---- */
    uint32_t qfh[4][4], qfl[4][4];
#pragma unroll
    for (int kb = 0; kb < 4; kb++)
#pragma unroll
        for (int i = 0; i < 4; i++) {
            const int row = ((i & 1) << 3) + (lane >> 2);
            const int kofs = kb * 16 + ((i >> 1) << 3) + ((lane & 3) << 1);
            int qg = q0 + wid * 16 + row;
            if (qg > SEQ - 1) qg = SEQ - 1;
            const float2 qv = *(const float2*)(qsrc + (size_t)(b * SEQ + qg) * DIM
                                               + h * HD + kofs);
            const float sx = qv.x * 0.125f, sy = qv.y * 0.125f;
            const float hx = bflo(sx), hy = bflo(sy);
            qfh[kb][i] = packbf(hx, hy);
            qfl[kb][i] = packbf(sx - hx, sy - hy);
        }

    /* K/V tile loader: 4 arrays x 64 rows x 8 chunks = 2048 cp16 per tile */
    const __nv_bfloat16* srcs[4];
    {
        const size_t base = ((size_t)(b * NH + h) * SEQ) * HD;
        srcs[0] = kh_g + base; srcs[1] = kl_g + base;
        srcs[2] = vh_g + base; srcs[3] = vl_g + base;
    }
    auto load_kv = [&](int kt, int buf) {
        __nv_bfloat16* dst = BUF(buf);
#pragma unroll
        for (int t = 0; t < 8; t++) {
            const int id = tid + t * 256;
            const int arr = id >> 9, rem = id & 511;
            const int row = rem >> 3, c = rem & 7;
            cp16(smem_u32(dst + arr * TILE_HALVES + row * KP + c * 8),
                 srcs[arr] + (size_t)(kt * ATK + row) * HD + c * 8);
        }
        asm volatile("cp.async.commit_group;" ::: "memory");
    };

    float m_lo = -1e30f, m_hi = -1e30f, l_lo = 0.f, l_hi = 0.f;
    float oacc[8][4];
#pragma unroll
    for (int nf = 0; nf < 8; nf++)
#pragma unroll
        for (int q = 0; q < 4; q++) oacc[nf][q] = 0.f;

    load_kv(0, 0);

    int buf = 0;
    for (int kt = 0; kt < ANKT; kt++) {
        asm volatile("cp.async.wait_group 0;" ::: "memory");
        __syncthreads();
        if (kt + 1 < ANKT) load_kv(kt + 1, buf ^ 1);

        const __nv_bfloat16* kh = BUF(buf);
        const __nv_bfloat16* kl = kh + TILE_HALVES;
        const __nv_bfloat16* vh = kh + 2 * TILE_HALVES;
        const __nv_bfloat16* vl = kh + 3 * TILE_HALVES;

        /* ---- S = Q K^T (3-product split) ---- */
        float sacc[8][4];
#pragma unroll
        for (int nf = 0; nf < 8; nf++)
#pragma unroll
            for (int q = 0; q < 4; q++) sacc[nf][q] = 0.f;

#pragma unroll
        for (int ks = 0; ks < 4; ks++) {
            uint32_t bh[4][4], bl[4][4];
#pragma unroll
            for (int np = 0; np < 4; np++) {
                const int roff = (np * 16 + ((lane >> 4) << 3) + (lane & 7)) * KP
                               + ks * 16 + (((lane >> 3) & 1) << 3);
                ldmx4(bh[np], kh + roff);
                ldmx4(bl[np], kl + roff);
            }
#pragma unroll
            for (int nf = 0; nf < 8; nf++) {
                const uint32_t b0h = bh[nf >> 1][(nf & 1) * 2];
                const uint32_t b1h = bh[nf >> 1][(nf & 1) * 2 + 1];
                const uint32_t b0l = bl[nf >> 1][(nf & 1) * 2];
                const uint32_t b1l = bl[nf >> 1][(nf & 1) * 2 + 1];
                mma16816(sacc[nf], qfh[ks], b0h, b1h);
                mma16816(sacc[nf], qfh[ks], b0l, b1l);
                mma16816(sacc[nf], qfl[ks], b0h, b1h);
            }
        }

        if (kt == ANKT - 1) {
#pragma unroll
            for (int nf = 2; nf < 8; nf++)
#pragma unroll
                for (int q = 0; q < 4; q++) sacc[nf][q] = -1e30f;
        }

        /* ---- online softmax ---- */
        float tmlo = -1e30f, tmhi = -1e30f;
#pragma unroll
        for (int nf = 0; nf < 8; nf++) {
            tmlo = fmaxf(tmlo, fmaxf(sacc[nf][0], sacc[nf][1]));
            tmhi = fmaxf(tmhi, fmaxf(sacc[nf][2], sacc[nf][3]));
        }
        tmlo = fmaxf(tmlo, __shfl_xor_sync(0xffffffff, tmlo, 1));
        tmlo = fmaxf(tmlo, __shfl_xor_sync(0xffffffff, tmlo, 2));
        tmhi = fmaxf(tmhi, __shfl_xor_sync(0xffffffff, tmhi, 1));
        tmhi = fmaxf(tmhi, __shfl_xor_sync(0xffffffff, tmhi, 2));

        const float nm_lo = fmaxf(m_lo, tmlo), nm_hi = fmaxf(m_hi, tmhi);
        const float a_lo = __expf(m_lo - nm_lo), a_hi = __expf(m_hi - nm_hi);
        m_lo = nm_lo; m_hi = nm_hi;

        float sum_lo = 0.f, sum_hi = 0.f;
#pragma unroll
        for (int nf = 0; nf < 8; nf++) {
            sacc[nf][0] = __expf(sacc[nf][0] - nm_lo);
            sacc[nf][1] = __expf(sacc[nf][1] - nm_lo);
            sacc[nf][2] = __expf(sacc[nf][2] - nm_hi);
            sacc[nf][3] = __expf(sacc[nf][3] - nm_hi);
            sum_lo += sacc[nf][0] + sacc[nf][1];
            sum_hi += sacc[nf][2] + sacc[nf][3];
        }
        sum_lo += __shfl_xor_sync(0xffffffff, sum_lo, 1);
        sum_lo += __shfl_xor_sync(0xffffffff, sum_lo, 2);
        sum_hi += __shfl_xor_sync(0xffffffff, sum_hi, 1);
        sum_hi += __shfl_xor_sync(0xffffffff, sum_hi, 2);
        l_lo = l_lo * a_lo + sum_lo;
        l_hi = l_hi * a_hi + sum_hi;

#pragma unroll
        for (int nf = 0; nf < 8; nf++) {
            oacc[nf][0] *= a_lo; oacc[nf][1] *= a_lo;
            oacc[nf][2] *= a_hi; oacc[nf][3] *= a_hi;
        }

        /* ---- O += P V (3-product split) ---- */
#pragma unroll
        for (int ks = 0; ks < 4; ks++) {
            uint32_t ph[4], pl[4];
            {
                const float* s0 = sacc[2 * ks];
                const float* s1 = sacc[2 * ks + 1];
                float h0 = bflo(s0[0]), h1 = bflo(s0[1]),
                      h2 = bflo(s0[2]), h3 = bflo(s0[3]);
                ph[0] = packbf(h0, h1);  ph[1] = packbf(h2, h3);
                pl[0] = packbf(s0[0] - h0, s0[1] - h1);
                pl[1] = packbf(s0[2] - h2, s0[3] - h3);
                h0 = bflo(s1[0]); h1 = bflo(s1[1]); h2 = bflo(s1[2]); h3 = bflo(s1[3]);
                ph[2] = packbf(h0, h1);  ph[3] = packbf(h2, h3);
                pl[2] = packbf(s1[0] - h0, s1[1] - h1);
                pl[3] = packbf(s1[2] - h2, s1[3] - h3);
            }
            uint32_t wh[4][4], wl[4][4];
#pragma unroll
            for (int np = 0; np < 4; np++) {
                const int roff = (ks * 16 + (lane & 7) + (((lane >> 3) & 1) << 3)) * KP
                               + np * 16 + (((lane >> 4) & 1) << 3);
                ldmx4t(wh[np], vh + roff);
                ldmx4t(wl[np], vl + roff);
            }
#pragma unroll
            for (int nf = 0; nf < 8; nf++) {
                const uint32_t b0h = wh[nf >> 1][(nf & 1) * 2];
                const uint32_t b1h = wh[nf >> 1][(nf & 1) * 2 + 1];
                const uint32_t b0l = wl[nf >> 1][(nf & 1) * 2];
                const uint32_t b1l = wl[nf >> 1][(nf & 1) * 2 + 1];
                mma16816(oacc[nf], ph, b0h, b1h);
                mma16816(oacc[nf], ph, b0l, b1l);
                mma16816(oacc[nf], pl, b0h, b1h);
            }
        }
        buf ^= 1;
    }

    /* normalize + write bf16 hi/lo (feeds out-proj split-GEMM) */
    const float inv_lo = 1.f / l_lo, inv_hi = 1.f / l_hi;
    const int r_lo = q0 + wid * 16 + (lane >> 2);
    const int r_hi = r_lo + 8;
#pragma unroll
    for (int nf = 0; nf < 8; nf++) {
        const int col = h * HD + nf * 8 + (lane & 3) * 2;
        if (r_lo < SEQ) {
            const float v0 = oacc[nf][0] * inv_lo, v1 = oacc[nf][1] * inv_lo;
            const float hx = bflo(v0), hy = bflo(v1);
            *(uint32_t*)(oh + (size_t)(b * SEQ + r_lo) * DIM + col) = packbf(hx, hy);
            *(uint32_t*)(ol + (size_t)(b * SEQ + r_lo) * DIM + col) =
                packbf(v0 - hx, v1 - hy);
        }
        if (r_hi < SEQ) {
            const float v0 = oacc[nf][2] * inv_hi, v1 = oacc[nf][3] * inv_hi;
            const float hx = bflo(v0), hy = bflo(v1);
            *(uint32_t*)(oh + (size_t)(b * SEQ + r_hi) * DIM + col) = packbf(hx, hy);
            *(uint32_t*)(ol + (size_t)(b * SEQ + r_hi) * DIM + col) =
                packbf(v0 - hx, v1 - hy);
        }
    }
}

/* ================================ launch =================================== */
extern "C" void kernel_launch(void* const* d_in, const int* in_sizes, int n_in,
                              void* d_out, int out_size)
{
    const float* x    = (const float*)d_in[0];
    const float* Wqkv = (const float*)d_in[1];
    const float* bqkv = (const float*)d_in[2];
    const float* Wo   = (const float*)d_in[3];
    const float* bo   = (const float*)d_in[4];
    float* out = (float*)d_out;

    float *q;
    __nv_bfloat16 *kh, *kl, *vh, *vl, *xh, *xl, *ath, *atl, *wqh, *wql, *woh, *wol;
    cudaGetSymbolAddress((void**)&q,   g_q);
    cudaGetSymbolAddress((void**)&kh,  g_kh);
    cudaGetSymbolAddress((void**)&kl,  g_kl);
    cudaGetSymbolAddress((void**)&vh,  g_vh);
    cudaGetSymbolAddress((void**)&vl,  g_vl);
    cudaGetSymbolAddress((void**)&xh,  g_xh);
    cudaGetSymbolAddress((void**)&xl,  g_xl);
    cudaGetSymbolAddress((void**)&ath, g_ath);
    cudaGetSymbolAddress((void**)&atl, g_atl);
    cudaGetSymbolAddress((void**)&wqh, g_wqh);
    cudaGetSymbolAddress((void**)&wql, g_wql);
    cudaGetSymbolAddress((void**)&woh, g_woh);
    cudaGetSymbolAddress((void**)&wol, g_wol);

    cudaFuncSetAttribute(mma_gemm_kernel, cudaFuncAttributeMaxDynamicSharedMemorySize,
                         GEMM_SMEM);
    cudaFuncSetAttribute(attn_mma_kernel, cudaFuncAttributeMaxDynamicSharedMemorySize,
                         ATT_SMEM);

    /* split x into bf16 hi/lo */
    {
        const int n4 = M_TOTAL * DIM / 4;
        split_kernel<<<(n4 + 255) / 256, 256>>>((const float4*)x,
                                                (__nv_bfloat162*)xh,
                                                (__nv_bfloat162*)xl, n4);
    }
    /* transpose+split weights */
    transpose_split_kernel<<<dim3(QKV_N / 32, DIM / 32), 256>>>(Wqkv, wqh, wql, DIM, QKV_N);
    transpose_split_kernel<<<dim3(DIM / 32, DIM / 32), 256>>>(Wo, woh, wol, DIM, DIM);

    /* 1) QKV projection, scattering epilogue: q fp32 + split K/V bf16 */
    mma_gemm_kernel<<<dim3(QKV_N / 128, M_TOTAL / 128), 256, GEMM_SMEM>>>(
        xh, xl, wqh, wql, bqkv, q, DIM, 1, kh, kl, vh, vl);

    /* 2) tensor-core split flash attention (prepacked K/V) */
    attn_mma_kernel<<<dim3(NQT, NH, BATCH), 256, ATT_SMEM>>>(
        q, kh, kl, vh, vl, ath, atl);

    /* 3) output projection */
    mma_gemm_kernel<<<dim3(DIM / 128, M_TOTAL / 128), 256, GEMM_SMEM>>>(
        ath, atl, woh, wol, bo, out, DIM, 0,
        nullptr, nullptr, nullptr, nullptr);
}